// round 7
// baseline (speedup 1.0000x reference)
#include <cuda_runtime.h>
#include <cuda_bf16.h>
#include <math.h>

#define NREV 4096
#define LTOK 128
#define DW   200
#define AASP 32
#define NNEG 5
#define BUSR 1024

// ---------------- scratch (device globals) -----------------------------------
__device__ __align__(16) float g_q[NREV * DW];
__device__ __align__(16) float g_rs[NREV * DW];
__device__ float g_hinge[NREV];
__device__ float g_sq[BUSR];
__device__ float g_U[1];
__device__ unsigned int g_cnt;

__device__ __forceinline__ float dot4(float4 a, float4 b) {
    return a.x * b.x + a.y * b.y + a.z * b.z + a.w * b.w;
}
__device__ __forceinline__ float warp_sum(float v) {
    #pragma unroll
    for (int o = 16; o; o >>= 1) v += __shfl_down_sync(0xffffffffu, v, o);
    return v;
}
__device__ __forceinline__ uint2 pack_bf16x4(float4 v) {
    __nv_bfloat162 a = __float22bfloat162_rn(make_float2(v.x, v.y));
    __nv_bfloat162 b = __float22bfloat162_rn(make_float2(v.z, v.w));
    uint2 u;
    u.x = *(unsigned int*)&a;
    u.y = *(unsigned int*)&b;
    return u;
}
// ---- f32x2 packed math (sm_103a) ----
__device__ __forceinline__ unsigned long long pk2(float x, float y) {
    unsigned long long r;
    asm("mov.b64 %0, {%1, %2};" : "=l"(r) : "f"(x), "f"(y));
    return r;
}
__device__ __forceinline__ float2 upk2(unsigned long long v) {
    float2 f;
    asm("mov.b64 {%0, %1}, %2;" : "=f"(f.x), "=f"(f.y) : "l"(v));
    return f;
}
__device__ __forceinline__ unsigned long long fma2(unsigned long long a,
                                                   unsigned long long b,
                                                   unsigned long long c) {
    unsigned long long d;
    asm("fma.rn.f32x2 %0, %1, %2, %3;" : "=l"(d) : "l"(a), "l"(b), "l"(c));
    return d;
}

// ---------------- K1: q = rev_pos @ M_w (vectorized) -------------------------
__global__ __launch_bounds__(256, 1)
void qk(const float* __restrict__ rp, const float* __restrict__ Mw) {
    extern __shared__ float sm[];
    float* Ms  = sm;            // 40000
    float* rps = sm + DW * DW;  // 6400
    int tid = threadIdx.x, w = tid >> 5, lane = tid & 31;
    for (int i = tid; i < DW * DW; i += 256) Ms[i] = Mw[i];
    int n0 = blockIdx.x * 32;
    for (int i = tid; i < 32 * DW; i += 256) rps[i] = rp[n0 * DW + i];
    __syncthreads();

    const float4* Ms4  = (const float4*)Ms;
    const float4* rps4 = (const float4*)rps;
    bool hi = (lane < 18);

    float4 acc[4][2];
    #pragma unroll
    for (int j = 0; j < 4; j++) {
        acc[j][0] = make_float4(0, 0, 0, 0);
        acc[j][1] = make_float4(0, 0, 0, 0);
    }

    for (int d2b = 0; d2b < 50; d2b++) {
        float4 r4[4];
        #pragma unroll
        for (int j = 0; j < 4; j++) r4[j] = rps4[(w * 4 + j) * 50 + d2b];
        #pragma unroll
        for (int s = 0; s < 4; s++) {
            int d2 = d2b * 4 + s;
            float4 m0 = Ms4[d2 * 50 + lane];
            float4 m1 = hi ? Ms4[d2 * 50 + 32 + lane] : make_float4(0, 0, 0, 0);
            #pragma unroll
            for (int j = 0; j < 4; j++) {
                float r = (s == 0) ? r4[j].x : (s == 1) ? r4[j].y : (s == 2) ? r4[j].z : r4[j].w;
                acc[j][0].x += r * m0.x; acc[j][0].y += r * m0.y;
                acc[j][0].z += r * m0.z; acc[j][0].w += r * m0.w;
                acc[j][1].x += r * m1.x; acc[j][1].y += r * m1.y;
                acc[j][1].z += r * m1.z; acc[j][1].w += r * m1.w;
            }
        }
    }
    float4* gq4 = (float4*)g_q;
    #pragma unroll
    for (int j = 0; j < 4; j++) {
        int row = (n0 + w * 4 + j) * 50;
        gq4[row + lane] = acc[j][0];
        if (hi) gq4[row + 32 + lane] = acc[j][1];
    }
}

// ---------------- K2: fused per-review ABAE, bf16 SMEM tile, occ 4 ------------
// SMEM floats: e_bf16 [0..12799] | qs 12800 | ax 13000 | zs 13128 | p 13328 |
//              part 13360 | tot 13464 | tok(int) 13480..13607
#define SM_WORDS 13608

__global__ __launch_bounds__(256, 4)
void mainkern(const int* __restrict__ hist, const float* __restrict__ wemb,
              const float* __restrict__ rneg, const float* __restrict__ Ww,
              const float* __restrict__ Wb, const float* __restrict__ Tw) {
    extern __shared__ float sm[];
    int n = blockIdx.x;
    int tid = threadIdx.x, w = tid >> 5, lane = tid & 31;

    // -------- extra block: U_loss --------
    if (n == NREV) {
        float* Ts  = sm;          // 6400
        float* nrm = sm + 6400;   // 32
        float* red = sm + 6432;   // 8
        for (int i = tid; i < DW * AASP; i += 256) Ts[i] = Tw[i];
        __syncthreads();
        if (tid < AASP) {
            float s = 0.f;
            for (int d = 0; d < DW; d++) { float v = Ts[d * AASP + tid]; s += v * v; }
            nrm[tid] = fmaxf(sqrtf(s), 1e-12f);
        }
        __syncthreads();
        float part = 0.f;
        for (int pr = tid; pr < AASP * AASP; pr += 256) {
            int a = pr >> 5, b = pr & 31;
            float s = 0.f;
            for (int d = 0; d < DW; d++) s += Ts[d * AASP + a] * Ts[d * AASP + b];
            float g = s / (nrm[a] * nrm[b]);
            float diff = g - ((a == b) ? 1.f : 0.f);
            part += diff * diff;
        }
        float v = warp_sum(part);
        if (lane == 0) red[w] = v;
        __syncthreads();
        if (tid == 0) {
            float t = 0.f;
            for (int k = 0; k < 8; k++) t += red[k];
            g_U[0] = t / (float)(AASP * AASP);
        }
        return;
    }

    uint2* eb2  = (uint2*)sm;
    float* qs   = sm + 12800;
    float* ax   = sm + 13000;
    float* zs   = sm + 13128;
    float* p    = sm + 13328;
    float* part = sm + 13360;
    float* tot  = sm + 13464;
    int*   tok  = (int*)(sm + 13480);

    if (tid < LTOK) tok[tid] = hist[n * LTOK + tid];
    if (tid < DW)   qs[tid]  = g_q[n * DW + tid];
    __syncthreads();

    bool hi = (lane < 18);
    const float4* qs4 = (const float4*)qs;
    float4 qv0 = qs4[lane];
    float4 qv1 = hi ? qs4[32 + lane] : make_float4(0, 0, 0, 0);
    unsigned long long q01 = pk2(qv0.x, qv0.y), q23 = pk2(qv0.z, qv0.w);
    unsigned long long q45 = pk2(qv1.x, qv1.y), q67 = pk2(qv1.z, qv1.w);
    const float4* we4 = (const float4*)wemb;

    // -------- single gather + dx (f32x2) + bf16 tile store --------
    #pragma unroll
    for (int t0 = 0; t0 < 16; t0 += 4) {
        float4 v0[4], v1[4];
        #pragma unroll
        for (int t = 0; t < 4; t++) {
            int rb = tok[w * 16 + t0 + t] * 50;
            v0[t] = __ldg(&we4[rb + lane]);
            v1[t] = hi ? __ldg(&we4[rb + 32 + lane]) : make_float4(0, 0, 0, 0);
        }
        float a[4];
        #pragma unroll
        for (int t = 0; t < 4; t++) {
            int l = w * 16 + t0 + t;
            eb2[l * 50 + lane] = pack_bf16x4(v0[t]);
            if (hi) eb2[l * 50 + 32 + lane] = pack_bf16x4(v1[t]);
            unsigned long long acc2 = fma2(pk2(v0[t].x, v0[t].y), q01,
                                     fma2(pk2(v0[t].z, v0[t].w), q23,
                                     fma2(pk2(v1[t].x, v1[t].y), q45,
                                     fma2(pk2(v1[t].z, v1[t].w), q67, 0ull))));
            float2 f = upk2(acc2);
            a[t] = f.x + f.y;
        }
        #pragma unroll
        for (int t = 0; t < 4; t++) a[t] = warp_sum(a[t]);
        if (lane == 0) {
            #pragma unroll
            for (int t = 0; t < 4; t++) ax[w * 16 + t0 + t] = a[t];
        }
    }
    __syncthreads();

    // -------- per-warp redundant softmax over 128 tokens (no extra barrier) --
    unsigned long long av01, av23;
    float4 av;
    {
        const float4* ax4 = (const float4*)ax;
        float4 axv = ax4[lane];
        float m = fmaxf(fmaxf(axv.x, axv.y), fmaxf(axv.z, axv.w));
        #pragma unroll
        for (int o = 16; o; o >>= 1) m = fmaxf(m, __shfl_xor_sync(0xffffffffu, m, o));
        float e0 = expf(axv.x - m), e1 = expf(axv.y - m);
        float e2 = expf(axv.z - m), e3 = expf(axv.w - m);
        float s = (e0 + e1) + (e2 + e3);
        #pragma unroll
        for (int o = 16; o; o >>= 1) s += __shfl_xor_sync(0xffffffffu, s, o);
        float inv = 1.f / s;
        av = make_float4(e0 * inv, e1 * inv, e2 * inv, e3 * inv);
        av01 = pk2(av.x, av.y); av23 = pk2(av.z, av.w);
    }

    // -------- z_s from bf16 SMEM tile (reshape trick, f32x2) --------
    #pragma unroll
    for (int j0 = 0; j0 < 24; j0 += 4) {
        float a[4];
        #pragma unroll
        for (int k = 0; k < 4; k++) {
            int d = w + 8 * (j0 + k);
            uint2 u = eb2[d * 32 + lane];
            float2 f0 = __bfloat1622float2(*(__nv_bfloat162*)&u.x);
            float2 f1 = __bfloat1622float2(*(__nv_bfloat162*)&u.y);
            float2 r = upk2(fma2(pk2(f0.x, f0.y), av01,
                           fma2(pk2(f1.x, f1.y), av23, 0ull)));
            a[k] = r.x + r.y;
        }
        #pragma unroll
        for (int k = 0; k < 4; k++) a[k] = warp_sum(a[k]);
        if (lane == 0) {
            #pragma unroll
            for (int k = 0; k < 4; k++) zs[w + 8 * (j0 + k)] = a[k];
        }
    }
    {   // leftover d = 192 + w
        int d = 192 + w;
        uint2 u = eb2[d * 32 + lane];
        float2 f0 = __bfloat1622float2(*(__nv_bfloat162*)&u.x);
        float2 f1 = __bfloat1622float2(*(__nv_bfloat162*)&u.y);
        float2 r = upk2(fma2(pk2(f0.x, f0.y), av01,
                       fma2(pk2(f1.x, f1.y), av23, 0ull)));
        float a = warp_sum(r.x + r.y);
        if (lane == 0) zs[d] = a;
    }
    __syncthreads();

    // -------- prefetch negatives (consumed at the end) --------
    float ng[NNEG];
    #pragma unroll
    for (int k = 0; k < NNEG; k++) ng[k] = 0.f;
    if (tid < DW) {
        #pragma unroll
        for (int k = 0; k < NNEG; k++)
            ng[k] = __ldg(&rneg[(n * NNEG + k) * DW + tid]);
    }

    // -------- logits = z_s @ W_w^T + W_b (warp w: aspects w+8j) --------
    {
        const float4* zs4 = (const float4*)zs;
        float4 zv0 = zs4[lane];
        float4 zv1 = hi ? zs4[32 + lane] : make_float4(0, 0, 0, 0);
        #pragma unroll
        for (int j = 0; j < 4; j++) {
            int a = w + 8 * j;
            const float4* wr = (const float4*)(Ww + a * DW);
            float acc = dot4(__ldg(&wr[lane]), zv0);
            if (hi) acc += dot4(__ldg(&wr[32 + lane]), zv1);
            acc = warp_sum(acc);
            if (lane == 0) p[a] = acc + Wb[a];
        }
    }
    __syncthreads();

    // -------- softmax over A=32 (warp 0) --------
    if (w == 0) {
        float v = p[lane];
        float m = v;
        #pragma unroll
        for (int o = 16; o; o >>= 1) m = fmaxf(m, __shfl_xor_sync(0xffffffffu, m, o));
        float ex = expf(v - m);
        float s = ex;
        #pragma unroll
        for (int o = 16; o; o >>= 1) s += __shfl_xor_sync(0xffffffffu, s, o);
        p[lane] = ex / s;
    }
    __syncthreads();

    // -------- r_s = p @ T_w^T ; 13 fused dots --------
    float rsv = 0.f, zsv = 0.f;
    if (tid < DW) {
        const float4* T4 = (const float4*)(Tw + tid * AASP);
        float acc = 0.f;
        #pragma unroll
        for (int j = 0; j < 8; j++) {
            float4 t = __ldg(&T4[j]);
            acc += t.x * p[j * 4 + 0] + t.y * p[j * 4 + 1]
                 + t.z * p[j * 4 + 2] + t.w * p[j * 4 + 3];
        }
        g_rs[n * DW + tid] = acc;
        rsv = acc;
        zsv = zs[tid];
    }

    float v[13];
    v[0] = zsv * zsv; v[1] = rsv * rsv; v[2] = zsv * rsv;
    #pragma unroll
    for (int k = 0; k < NNEG; k++) { v[3 + k] = ng[k] * ng[k]; v[8 + k] = ng[k] * rsv; }
    #pragma unroll
    for (int x = 0; x < 13; x++) v[x] = warp_sum(v[x]);
    if (lane == 0) {
        #pragma unroll
        for (int x = 0; x < 13; x++) part[w * 13 + x] = v[x];
    }
    __syncthreads();
    if (w == 0 && lane < 13) {
        float s = 0.f;
        #pragma unroll
        for (int k = 0; k < 8; k++) s += part[k * 13 + lane];
        tot[lane] = s;
    }
    __syncthreads();
    if (tid == 0) {
        float nz = fmaxf(sqrtf(tot[0]), 1e-12f);
        float nr = fmaxf(sqrtf(tot[1]), 1e-12f);
        float c1 = tot[2] / (nz * nr);
        float h = 0.f;
        #pragma unroll
        for (int k = 0; k < NNEG; k++) {
            float c2 = tot[8 + k] / (fmaxf(sqrtf(tot[3 + k]), 1e-12f) * nr);
            h += fmaxf(0.f, c2 - c1);
        }
        g_hinge[n] = h;
    }
}

// ---------------- K3: fused segment means + prediction + final reduce ---------
__global__ __launch_bounds__(256, 8)
void segpredfin(const int* __restrict__ uhi, const int* __restrict__ usi,
                const int* __restrict__ ihi, const int* __restrict__ isi,
                const float* __restrict__ label, int F, float* __restrict__ out) {
    int b = blockIdx.x;
    int tid = threadIdx.x, w = tid >> 5, lane = tid & 31;
    __shared__ int bnd[4];
    __shared__ float red[8];
    __shared__ unsigned int rank;
    if (tid < 2) {
        const int* seg = tid ? isi : usi;
        int lo = 0, hi = F;
        while (lo < hi) { int m = (lo + hi) >> 1; if (seg[m] < b) lo = m + 1; else hi = m; }
        bnd[tid * 2] = lo;
        int lo2 = lo, hi2 = F;
        while (lo2 < hi2) { int m = (lo2 + hi2) >> 1; if (seg[m] < b + 1) lo2 = m + 1; else hi2 = m; }
        bnd[tid * 2 + 1] = lo2;
    }
    __syncthreads();

    float prod = 0.f;
    int d = tid;
    if (d < DW) {
        float um, im;
        {
            int lo = bnd[0], cnt = bnd[1] - bnd[0];
            float s0 = 0.f, s1 = 0.f, s2 = 0.f, s3 = 0.f;
            int j = 0;
            for (; j + 4 <= cnt; j += 4) {
                s0 += g_rs[uhi[lo + j] * DW + d];
                s1 += g_rs[uhi[lo + j + 1] * DW + d];
                s2 += g_rs[uhi[lo + j + 2] * DW + d];
                s3 += g_rs[uhi[lo + j + 3] * DW + d];
            }
            for (; j < cnt; j++) s0 += g_rs[uhi[lo + j] * DW + d];
            um = ((s0 + s1) + (s2 + s3)) / (float)cnt;
        }
        {
            int lo = bnd[2], cnt = bnd[3] - bnd[2];
            float s0 = 0.f, s1 = 0.f, s2 = 0.f, s3 = 0.f;
            int j = 0;
            for (; j + 4 <= cnt; j += 4) {
                s0 += g_rs[ihi[lo + j] * DW + d];
                s1 += g_rs[ihi[lo + j + 1] * DW + d];
                s2 += g_rs[ihi[lo + j + 2] * DW + d];
                s3 += g_rs[ihi[lo + j + 3] * DW + d];
            }
            for (; j < cnt; j++) s0 += g_rs[ihi[lo + j] * DW + d];
            im = ((s0 + s1) + (s2 + s3)) / (float)cnt;
        }
        prod = um * im;
    }
    float s = warp_sum(prod);
    if (lane == 0) red[w] = s;
    __syncthreads();
    if (tid == 0) {
        float t = 0.f;
        #pragma unroll
        for (int k = 0; k < 8; k++) t += red[k];
        float e = t + 3.5f - label[b];
        g_sq[b] = e * e;
        __threadfence();
        rank = atomicAdd(&g_cnt, 1u);
    }
    __syncthreads();

    // last block performs the final reduction
    if (rank == BUSR - 1) {
        __threadfence();
        float hsum = 0.f;
        for (int i = tid; i < NREV; i += 256) hsum += g_hinge[i];
        hsum = warp_sum(hsum);
        if (lane == 0) red[w] = hsum;
        __syncthreads();
        float hs = 0.f;
        if (tid == 0) for (int k = 0; k < 8; k++) hs += red[k];
        __syncthreads();

        float s2 = 0.f;
        for (int i = tid; i < BUSR; i += 256) s2 += g_sq[i];
        s2 = warp_sum(s2);
        if (lane == 0) red[w] = s2;
        __syncthreads();
        if (tid == 0) {
            float rsum = 0.f;
            for (int k = 0; k < 8; k++) rsum += red[k];
            float rating = rsum / (float)BUSR;
            float J = hs / (float)(NREV * NNEG);
            float abae = g_U[0] + J;
            out[0] = rating + abae;
            out[1] = rating;
            out[2] = abae;
            g_cnt = 0u;   // reset for next (graph-replayed) call
        }
    }
}

// ---------------- launch ------------------------------------------------------
extern "C" void kernel_launch(void* const* d_in, const int* in_sizes, int n_in,
                              void* d_out, int out_size) {
    const int*   hist  = (const int*)d_in[0];
    const float* rpos  = (const float*)d_in[1];
    const float* rneg  = (const float*)d_in[2];
    const float* label = (const float*)d_in[5];
    const int*   uhi   = (const int*)d_in[6];
    const int*   usi   = (const int*)d_in[7];
    const int*   ihi   = (const int*)d_in[8];
    const int*   isi   = (const int*)d_in[9];
    const float* wemb  = (const float*)d_in[10];
    const float* Mw    = (const float*)d_in[11];
    const float* Ww    = (const float*)d_in[12];
    const float* Wb    = (const float*)d_in[13];
    const float* Tw    = (const float*)d_in[14];
    float* out = (float*)d_out;
    int F = in_sizes[6];

    const int SMEM_QK   = (DW * DW + 32 * DW) * 4;   // 185600 B
    const int SMEM_MAIN = SM_WORDS * 4;              // 54432 B
    cudaFuncSetAttribute(qk, cudaFuncAttributeMaxDynamicSharedMemorySize, SMEM_QK);
    cudaFuncSetAttribute(mainkern, cudaFuncAttributeMaxDynamicSharedMemorySize, SMEM_MAIN);

    qk<<<NREV / 32, 256, SMEM_QK>>>(rpos, Mw);
    mainkern<<<NREV + 1, 256, SMEM_MAIN>>>(hist, wemb, rneg, Ww, Wb, Tw);
    segpredfin<<<BUSR, 256>>>(uhi, usi, ihi, isi, label, F, out);
}

// round 8
// speedup vs baseline: 1.1183x; 1.1183x over previous
#include <cuda_runtime.h>
#include <cuda_bf16.h>
#include <math.h>

#define NREV 4096
#define LTOK 128
#define DW   200
#define AASP 32
#define NNEG 5
#define BUSR 1024

// ---------------- scratch (device globals) -----------------------------------
__device__ __align__(16) float g_q[NREV * DW];
__device__ __align__(16) float g_rs[NREV * DW];
__device__ float g_hinge[NREV];
__device__ float g_sq[BUSR];
__device__ float g_U[1];

__device__ __forceinline__ float dot4(float4 a, float4 b) {
    return a.x * b.x + a.y * b.y + a.z * b.z + a.w * b.w;
}
__device__ __forceinline__ float warp_sum(float v) {
    #pragma unroll
    for (int o = 16; o; o >>= 1) v += __shfl_down_sync(0xffffffffu, v, o);
    return v;
}
__device__ __forceinline__ uint2 pack_bf16x4(float4 v) {
    __nv_bfloat162 a = __float22bfloat162_rn(make_float2(v.x, v.y));
    __nv_bfloat162 b = __float22bfloat162_rn(make_float2(v.z, v.w));
    uint2 u;
    u.x = *(unsigned int*)&a;
    u.y = *(unsigned int*)&b;
    return u;
}
// ---- f32x2 packed math (sm_103a) ----
__device__ __forceinline__ unsigned long long pk2(float x, float y) {
    unsigned long long r;
    asm("mov.b64 %0, {%1, %2};" : "=l"(r) : "f"(x), "f"(y));
    return r;
}
__device__ __forceinline__ float2 upk2(unsigned long long v) {
    float2 f;
    asm("mov.b64 {%0, %1}, %2;" : "=f"(f.x), "=f"(f.y) : "l"(v));
    return f;
}
__device__ __forceinline__ unsigned long long fma2(unsigned long long a,
                                                   unsigned long long b,
                                                   unsigned long long c) {
    unsigned long long d;
    asm("fma.rn.f32x2 %0, %1, %2, %3;" : "=l"(d) : "l"(a), "l"(b), "l"(c));
    return d;
}

// ---------------- K1: q = rev_pos @ M_w --------------------------------------
// 512 threads, grid 128 (one wave). Warp w: reviews (w&7)*4..+3, output-chunk
// half h=w>>3 (chunk c = lane or 32+lane). r-loads are warp-broadcast LDS.
// f32x2 packed FMA halves FFMA issue count.
__global__ __launch_bounds__(512, 1)
void qk(const float* __restrict__ rp, const float* __restrict__ Mw) {
    extern __shared__ float sm[];
    float* Ms  = sm;            // 40000
    float* rps = sm + DW * DW;  // 6400
    int tid = threadIdx.x, w = tid >> 5, lane = tid & 31;
    {
        const float4* Mw4 = (const float4*)Mw;
        float4* Ms4w = (float4*)Ms;
        for (int i = tid; i < DW * DW / 4; i += 512) Ms4w[i] = __ldg(&Mw4[i]);
        int n0 = blockIdx.x * 32;
        const float4* rp4 = (const float4*)(rp + n0 * DW);
        float4* rps4w = (float4*)rps;
        for (int i = tid; i < 32 * DW / 4; i += 512) rps4w[i] = __ldg(&rp4[i]);
    }
    __syncthreads();

    int wg = w & 7;          // review group: 4 reviews
    int h  = w >> 3;         // chunk half
    bool act = (h == 0) || (lane < 18);
    int c = h ? (32 + (lane < 18 ? lane : 0)) : lane;   // clamp inactive lanes

    const float4* Ms4  = (const float4*)Ms;
    const float4* rps4 = (const float4*)rps;

    unsigned long long acc[4][2];
    #pragma unroll
    for (int j = 0; j < 4; j++) { acc[j][0] = 0ull; acc[j][1] = 0ull; }

    for (int d2b = 0; d2b < 50; d2b++) {
        float4 r4[4];
        #pragma unroll
        for (int j = 0; j < 4; j++) r4[j] = rps4[(wg * 4 + j) * 50 + d2b];  // broadcast
        #pragma unroll
        for (int s = 0; s < 4; s++) {
            float4 m = Ms4[(d2b * 4 + s) * 50 + c];
            unsigned long long m01 = pk2(m.x, m.y), m23 = pk2(m.z, m.w);
            #pragma unroll
            for (int j = 0; j < 4; j++) {
                float r = (s == 0) ? r4[j].x : (s == 1) ? r4[j].y
                        : (s == 2) ? r4[j].z : r4[j].w;
                unsigned long long rr = pk2(r, r);
                acc[j][0] = fma2(rr, m01, acc[j][0]);
                acc[j][1] = fma2(rr, m23, acc[j][1]);
            }
        }
    }

    if (act) {
        int n0 = blockIdx.x * 32;
        float4* gq4 = (float4*)g_q;
        #pragma unroll
        for (int j = 0; j < 4; j++) {
            float2 a0 = upk2(acc[j][0]), a1 = upk2(acc[j][1]);
            float4 o; o.x = a0.x; o.y = a0.y; o.z = a1.x; o.w = a1.y;
            gq4[(n0 + wg * 4 + j) * 50 + c] = o;
        }
    }
}

// ---------------- K2: fused per-review ABAE, bf16 SMEM tile, occ 4 ------------
// SMEM floats: e_bf16 [0..12799] | qs 12800 | ax 13000 | zs 13128 | p 13328 |
//              part 13360 | tot 13464 | tok(int) 13480..13607
#define SM_WORDS 13608

__global__ __launch_bounds__(256, 4)
void mainkern(const int* __restrict__ hist, const float* __restrict__ wemb,
              const float* __restrict__ rneg, const float* __restrict__ Ww,
              const float* __restrict__ Wb, const float* __restrict__ Tw) {
    extern __shared__ float sm[];
    int n = blockIdx.x;
    int tid = threadIdx.x, w = tid >> 5, lane = tid & 31;

    // -------- extra block: U_loss --------
    if (n == NREV) {
        float* Ts  = sm;          // 6400
        float* nrm = sm + 6400;   // 32
        float* red = sm + 6432;   // 8
        for (int i = tid; i < DW * AASP; i += 256) Ts[i] = Tw[i];
        __syncthreads();
        if (tid < AASP) {
            float s = 0.f;
            for (int d = 0; d < DW; d++) { float v = Ts[d * AASP + tid]; s += v * v; }
            nrm[tid] = fmaxf(sqrtf(s), 1e-12f);
        }
        __syncthreads();
        float part = 0.f;
        for (int pr = tid; pr < AASP * AASP; pr += 256) {
            int a = pr >> 5, b = pr & 31;
            float s = 0.f;
            for (int d = 0; d < DW; d++) s += Ts[d * AASP + a] * Ts[d * AASP + b];
            float g = s / (nrm[a] * nrm[b]);
            float diff = g - ((a == b) ? 1.f : 0.f);
            part += diff * diff;
        }
        float v = warp_sum(part);
        if (lane == 0) red[w] = v;
        __syncthreads();
        if (tid == 0) {
            float t = 0.f;
            for (int k = 0; k < 8; k++) t += red[k];
            g_U[0] = t / (float)(AASP * AASP);
        }
        return;
    }

    uint2* eb2  = (uint2*)sm;
    float* qs   = sm + 12800;
    float* ax   = sm + 13000;
    float* zs   = sm + 13128;
    float* p    = sm + 13328;
    float* part = sm + 13360;
    float* tot  = sm + 13464;
    int*   tok  = (int*)(sm + 13480);

    if (tid < LTOK) tok[tid] = hist[n * LTOK + tid];
    if (tid < DW)   qs[tid]  = g_q[n * DW + tid];
    __syncthreads();

    bool hi = (lane < 18);
    const float4* qs4 = (const float4*)qs;
    float4 qv0 = qs4[lane];
    float4 qv1 = hi ? qs4[32 + lane] : make_float4(0, 0, 0, 0);
    const float4* we4 = (const float4*)wemb;

    // -------- single gather + dx (fp32 exact) + bf16 tile store --------
    #pragma unroll
    for (int t0 = 0; t0 < 16; t0 += 4) {
        float4 v0[4], v1[4];
        #pragma unroll
        for (int t = 0; t < 4; t++) {
            int rb = tok[w * 16 + t0 + t] * 50;
            v0[t] = __ldg(&we4[rb + lane]);
            v1[t] = hi ? __ldg(&we4[rb + 32 + lane]) : make_float4(0, 0, 0, 0);
        }
        float a[4];
        #pragma unroll
        for (int t = 0; t < 4; t++) {
            int l = w * 16 + t0 + t;
            eb2[l * 50 + lane] = pack_bf16x4(v0[t]);
            if (hi) eb2[l * 50 + 32 + lane] = pack_bf16x4(v1[t]);
            a[t] = dot4(v0[t], qv0) + dot4(v1[t], qv1);
        }
        #pragma unroll
        for (int t = 0; t < 4; t++) a[t] = warp_sum(a[t]);
        if (lane == 0) {
            #pragma unroll
            for (int t = 0; t < 4; t++) ax[w * 16 + t0 + t] = a[t];
        }
    }
    __syncthreads();

    // -------- softmax over 128 tokens (warp 0) --------
    if (w == 0) {
        float v0 = ax[lane], v1 = ax[lane + 32], v2 = ax[lane + 64], v3 = ax[lane + 96];
        float m = fmaxf(fmaxf(v0, v1), fmaxf(v2, v3));
        #pragma unroll
        for (int o = 16; o; o >>= 1) m = fmaxf(m, __shfl_xor_sync(0xffffffffu, m, o));
        v0 = expf(v0 - m); v1 = expf(v1 - m); v2 = expf(v2 - m); v3 = expf(v3 - m);
        float s = v0 + v1 + v2 + v3;
        #pragma unroll
        for (int o = 16; o; o >>= 1) s += __shfl_xor_sync(0xffffffffu, s, o);
        float inv = 1.f / s;
        ax[lane] = v0 * inv; ax[lane + 32] = v1 * inv;
        ax[lane + 64] = v2 * inv; ax[lane + 96] = v3 * inv;
    }
    __syncthreads();

    // -------- z_s from bf16 SMEM tile (reshape trick, flat slices) --------
    {
        const float4* ax4 = (const float4*)ax;
        float4 av = ax4[lane];
        #pragma unroll
        for (int j0 = 0; j0 < 24; j0 += 4) {
            float a[4];
            #pragma unroll
            for (int k = 0; k < 4; k++) {
                int d = w + 8 * (j0 + k);
                uint2 u = eb2[d * 32 + lane];
                float2 f0 = __bfloat1622float2(*(__nv_bfloat162*)&u.x);
                float2 f1 = __bfloat1622float2(*(__nv_bfloat162*)&u.y);
                a[k] = f0.x * av.x + f0.y * av.y + f1.x * av.z + f1.y * av.w;
            }
            #pragma unroll
            for (int k = 0; k < 4; k++) a[k] = warp_sum(a[k]);
            if (lane == 0) {
                #pragma unroll
                for (int k = 0; k < 4; k++) zs[w + 8 * (j0 + k)] = a[k];
            }
        }
        {   // leftover d = 192 + w
            int d = 192 + w;
            uint2 u = eb2[d * 32 + lane];
            float2 f0 = __bfloat1622float2(*(__nv_bfloat162*)&u.x);
            float2 f1 = __bfloat1622float2(*(__nv_bfloat162*)&u.y);
            float a = warp_sum(f0.x * av.x + f0.y * av.y + f1.x * av.z + f1.y * av.w);
            if (lane == 0) zs[d] = a;
        }
    }
    __syncthreads();

    // -------- logits = z_s @ W_w^T + W_b (warp w: aspects w+8j) --------
    {
        const float4* zs4 = (const float4*)zs;
        float4 zv0 = zs4[lane];
        float4 zv1 = hi ? zs4[32 + lane] : make_float4(0, 0, 0, 0);
        #pragma unroll
        for (int j = 0; j < 4; j++) {
            int a = w + 8 * j;
            const float4* wr = (const float4*)(Ww + a * DW);
            float acc = dot4(__ldg(&wr[lane]), zv0);
            if (hi) acc += dot4(__ldg(&wr[32 + lane]), zv1);
            acc = warp_sum(acc);
            if (lane == 0) p[a] = acc + Wb[a];
        }
    }
    __syncthreads();

    // -------- softmax over A=32 (warp 0) --------
    if (w == 0) {
        float v = p[lane];
        float m = v;
        #pragma unroll
        for (int o = 16; o; o >>= 1) m = fmaxf(m, __shfl_xor_sync(0xffffffffu, m, o));
        float ex = expf(v - m);
        float s = ex;
        #pragma unroll
        for (int o = 16; o; o >>= 1) s += __shfl_xor_sync(0xffffffffu, s, o);
        p[lane] = ex / s;
    }
    __syncthreads();

    // -------- r_s = p @ T_w^T ; negatives direct; 13 fused dots --------
    float rsv = 0.f, zsv = 0.f, ng[NNEG];
    #pragma unroll
    for (int k = 0; k < NNEG; k++) ng[k] = 0.f;
    if (tid < DW) {
        #pragma unroll
        for (int k = 0; k < NNEG; k++)
            ng[k] = __ldg(&rneg[(n * NNEG + k) * DW + tid]);
        const float4* T4 = (const float4*)(Tw + tid * AASP);
        float acc = 0.f;
        #pragma unroll
        for (int j = 0; j < 8; j++) {
            float4 t = __ldg(&T4[j]);
            acc += t.x * p[j * 4 + 0] + t.y * p[j * 4 + 1]
                 + t.z * p[j * 4 + 2] + t.w * p[j * 4 + 3];
        }
        g_rs[n * DW + tid] = acc;
        rsv = acc;
        zsv = zs[tid];
    }

    float v[13];
    v[0] = zsv * zsv; v[1] = rsv * rsv; v[2] = zsv * rsv;
    #pragma unroll
    for (int k = 0; k < NNEG; k++) { v[3 + k] = ng[k] * ng[k]; v[8 + k] = ng[k] * rsv; }
    #pragma unroll
    for (int x = 0; x < 13; x++) v[x] = warp_sum(v[x]);
    if (lane == 0) {
        #pragma unroll
        for (int x = 0; x < 13; x++) part[w * 13 + x] = v[x];
    }
    __syncthreads();
    if (w == 0 && lane < 13) {
        float s = 0.f;
        #pragma unroll
        for (int k = 0; k < 8; k++) s += part[k * 13 + lane];
        tot[lane] = s;
    }
    __syncthreads();
    if (tid == 0) {
        float nz = fmaxf(sqrtf(tot[0]), 1e-12f);
        float nr = fmaxf(sqrtf(tot[1]), 1e-12f);
        float c1 = tot[2] / (nz * nr);
        float h = 0.f;
        #pragma unroll
        for (int k = 0; k < NNEG; k++) {
            float c2 = tot[8 + k] / (fmaxf(sqrtf(tot[3 + k]), 1e-12f) * nr);
            h += fmaxf(0.f, c2 - c1);
        }
        g_hinge[n] = h;
    }
}

// ---------------- K3: fused segment means + prediction ------------------------
__global__ __launch_bounds__(256, 8)
void segpred(const int* __restrict__ uhi, const int* __restrict__ usi,
             const int* __restrict__ ihi, const int* __restrict__ isi,
             const float* __restrict__ label, int F) {
    int b = blockIdx.x;
    int tid = threadIdx.x, w = tid >> 5, lane = tid & 31;
    __shared__ int bnd[4];
    __shared__ float red[8];
    if (tid < 2) {
        const int* seg = tid ? isi : usi;
        int lo = 0, hi = F;
        while (lo < hi) { int m = (lo + hi) >> 1; if (seg[m] < b) lo = m + 1; else hi = m; }
        bnd[tid * 2] = lo;
        int lo2 = lo, hi2 = F;
        while (lo2 < hi2) { int m = (lo2 + hi2) >> 1; if (seg[m] < b + 1) lo2 = m + 1; else hi2 = m; }
        bnd[tid * 2 + 1] = lo2;
    }
    __syncthreads();

    float prod = 0.f;
    int d = tid;
    if (d < DW) {
        float um, im;
        {
            int lo = bnd[0], cnt = bnd[1] - bnd[0];
            float s0 = 0.f, s1 = 0.f, s2 = 0.f, s3 = 0.f;
            int j = 0;
            for (; j + 4 <= cnt; j += 4) {
                s0 += g_rs[uhi[lo + j] * DW + d];
                s1 += g_rs[uhi[lo + j + 1] * DW + d];
                s2 += g_rs[uhi[lo + j + 2] * DW + d];
                s3 += g_rs[uhi[lo + j + 3] * DW + d];
            }
            for (; j < cnt; j++) s0 += g_rs[uhi[lo + j] * DW + d];
            um = ((s0 + s1) + (s2 + s3)) / (float)cnt;
        }
        {
            int lo = bnd[2], cnt = bnd[3] - bnd[2];
            float s0 = 0.f, s1 = 0.f, s2 = 0.f, s3 = 0.f;
            int j = 0;
            for (; j + 4 <= cnt; j += 4) {
                s0 += g_rs[ihi[lo + j] * DW + d];
                s1 += g_rs[ihi[lo + j + 1] * DW + d];
                s2 += g_rs[ihi[lo + j + 2] * DW + d];
                s3 += g_rs[ihi[lo + j + 3] * DW + d];
            }
            for (; j < cnt; j++) s0 += g_rs[ihi[lo + j] * DW + d];
            im = ((s0 + s1) + (s2 + s3)) / (float)cnt;
        }
        prod = um * im;
    }
    float s = warp_sum(prod);
    if (lane == 0) red[w] = s;
    __syncthreads();
    if (tid == 0) {
        float t = 0.f;
        #pragma unroll
        for (int k = 0; k < 8; k++) t += red[k];
        float e = t + 3.5f - label[b];
        g_sq[b] = e * e;
    }
}

// ---------------- K4: final reductions ----------------------------------------
__global__ __launch_bounds__(1024, 1)
void finkern(float* __restrict__ out) {
    __shared__ float sc[32];
    int tid = threadIdx.x, w = tid >> 5, lane = tid & 31;

    float s = 0.f;
    for (int i = tid; i < NREV; i += 1024) s += g_hinge[i];
    s = warp_sum(s);
    if (lane == 0) sc[w] = s;
    __syncthreads();
    float hs = 0.f;
    if (tid == 0) for (int k = 0; k < 32; k++) hs += sc[k];
    __syncthreads();

    float s2 = 0.f;
    for (int i = tid; i < BUSR; i += 1024) s2 += g_sq[i];
    s2 = warp_sum(s2);
    if (lane == 0) sc[w] = s2;
    __syncthreads();
    if (tid == 0) {
        float rsum = 0.f;
        for (int k = 0; k < 32; k++) rsum += sc[k];
        float rating = rsum / (float)BUSR;
        float J = hs / (float)(NREV * NNEG);
        float abae = g_U[0] + J;
        out[0] = rating + abae;
        out[1] = rating;
        out[2] = abae;
    }
}

// ---------------- launch ------------------------------------------------------
extern "C" void kernel_launch(void* const* d_in, const int* in_sizes, int n_in,
                              void* d_out, int out_size) {
    const int*   hist  = (const int*)d_in[0];
    const float* rpos  = (const float*)d_in[1];
    const float* rneg  = (const float*)d_in[2];
    const float* label = (const float*)d_in[5];
    const int*   uhi   = (const int*)d_in[6];
    const int*   usi   = (const int*)d_in[7];
    const int*   ihi   = (const int*)d_in[8];
    const int*   isi   = (const int*)d_in[9];
    const float* wemb  = (const float*)d_in[10];
    const float* Mw    = (const float*)d_in[11];
    const float* Ww    = (const float*)d_in[12];
    const float* Wb    = (const float*)d_in[13];
    const float* Tw    = (const float*)d_in[14];
    float* out = (float*)d_out;
    int F = in_sizes[6];

    const int SMEM_QK   = (DW * DW + 32 * DW) * 4;   // 185600 B
    const int SMEM_MAIN = SM_WORDS * 4;              // 54432 B
    cudaFuncSetAttribute(qk, cudaFuncAttributeMaxDynamicSharedMemorySize, SMEM_QK);
    cudaFuncSetAttribute(mainkern, cudaFuncAttributeMaxDynamicSharedMemorySize, SMEM_MAIN);

    qk<<<NREV / 32, 512, SMEM_QK>>>(rpos, Mw);
    mainkern<<<NREV + 1, 256, SMEM_MAIN>>>(hist, wemb, rneg, Ww, Wb, Tw);
    segpred<<<BUSR, 256>>>(uhi, usi, ihi, isi, label, F);
    finkern<<<1, 1024>>>(out);
}

// round 10
// speedup vs baseline: 1.2549x; 1.1221x over previous
#include <cuda_runtime.h>
#include <cuda_bf16.h>
#include <math.h>

#define NREV 4096
#define LTOK 128
#define DW   200
#define AASP 32
#define NNEG 5
#define BUSR 1024

// ---------------- scratch (device globals) -----------------------------------
__device__ __align__(16) float g_q[NREV * DW];
__device__ __align__(16) float g_rs[NREV * DW];
__device__ float g_hinge[NREV];
__device__ float g_sq[BUSR];
__device__ float g_U[1];
__device__ __align__(16) __nv_bfloat16 g_Wwb[AASP * DW];
__device__ __align__(16) __nv_bfloat16 g_Twb[DW * AASP];

__device__ __forceinline__ float dot4(float4 a, float4 b) {
    return a.x * b.x + a.y * b.y + a.z * b.z + a.w * b.w;
}
__device__ __forceinline__ float warp_sum(float v) {
    #pragma unroll
    for (int o = 16; o; o >>= 1) v += __shfl_down_sync(0xffffffffu, v, o);
    return v;
}
__device__ __forceinline__ uint2 pack_bf16x4(float4 v) {
    __nv_bfloat162 a = __float22bfloat162_rn(make_float2(v.x, v.y));
    __nv_bfloat162 b = __float22bfloat162_rn(make_float2(v.z, v.w));
    uint2 u;
    u.x = *(unsigned int*)&a;
    u.y = *(unsigned int*)&b;
    return u;
}
__device__ __forceinline__ float2 bf2f(unsigned int u) {
    return __bfloat1622float2(*(__nv_bfloat162*)&u);
}
// ---- f32x2 packed math (sm_103a) ----
__device__ __forceinline__ unsigned long long pk2(float x, float y) {
    unsigned long long r;
    asm("mov.b64 %0, {%1, %2};" : "=l"(r) : "f"(x), "f"(y));
    return r;
}
__device__ __forceinline__ float2 upk2(unsigned long long v) {
    float2 f;
    asm("mov.b64 {%0, %1}, %2;" : "=f"(f.x), "=f"(f.y) : "l"(v));
    return f;
}
__device__ __forceinline__ unsigned long long fma2(unsigned long long a,
                                                   unsigned long long b,
                                                   unsigned long long c) {
    unsigned long long d;
    asm("fma.rn.f32x2 %0, %1, %2, %3;" : "=l"(d) : "l"(a), "l"(b), "l"(c));
    return d;
}

// ---------------- K0: convert Ww/Tw to bf16 (overlaps qk) ---------------------
__global__ __launch_bounds__(256, 4)
void wconv(const float* __restrict__ Ww, const float* __restrict__ Tw) {
    int i = blockIdx.x * 256 + threadIdx.x;
    if (i < AASP * DW) {
        g_Wwb[i] = __float2bfloat16(Ww[i]);
        g_Twb[i] = __float2bfloat16(Tw[i]);
    }
}

// ---------------- K1: q = rev_pos @ M_w --------------------------------------
__global__ __launch_bounds__(512, 1)
void qk(const float* __restrict__ rp, const float* __restrict__ Mw) {
    extern __shared__ float sm[];
    float* Ms  = sm;            // 40000
    float* rps = sm + DW * DW;  // 6400
    int tid = threadIdx.x, w = tid >> 5, lane = tid & 31;
    {
        const float4* Mw4 = (const float4*)Mw;
        float4* Ms4w = (float4*)Ms;
        for (int i = tid; i < DW * DW / 4; i += 512) Ms4w[i] = __ldg(&Mw4[i]);
        int n0 = blockIdx.x * 32;
        const float4* rp4 = (const float4*)(rp + n0 * DW);
        float4* rps4w = (float4*)rps;
        for (int i = tid; i < 32 * DW / 4; i += 512) rps4w[i] = __ldg(&rp4[i]);
    }
    __syncthreads();

    int wg = w & 7;
    int h  = w >> 3;
    bool act = (h == 0) || (lane < 18);
    int c = h ? (32 + (lane < 18 ? lane : 0)) : lane;

    const float4* Ms4  = (const float4*)Ms;
    const float4* rps4 = (const float4*)rps;

    unsigned long long acc[4][2];
    #pragma unroll
    for (int j = 0; j < 4; j++) { acc[j][0] = 0ull; acc[j][1] = 0ull; }

    for (int d2b = 0; d2b < 50; d2b++) {
        float4 r4[4];
        #pragma unroll
        for (int j = 0; j < 4; j++) r4[j] = rps4[(wg * 4 + j) * 50 + d2b];
        #pragma unroll
        for (int s = 0; s < 4; s++) {
            float4 m = Ms4[(d2b * 4 + s) * 50 + c];
            unsigned long long m01 = pk2(m.x, m.y), m23 = pk2(m.z, m.w);
            #pragma unroll
            for (int j = 0; j < 4; j++) {
                float r = (s == 0) ? r4[j].x : (s == 1) ? r4[j].y
                        : (s == 2) ? r4[j].z : r4[j].w;
                unsigned long long rr = pk2(r, r);
                acc[j][0] = fma2(rr, m01, acc[j][0]);
                acc[j][1] = fma2(rr, m23, acc[j][1]);
            }
        }
    }

    if (act) {
        int n0 = blockIdx.x * 32;
        float4* gq4 = (float4*)g_q;
        #pragma unroll
        for (int j = 0; j < 4; j++) {
            float2 a0 = upk2(acc[j][0]), a1 = upk2(acc[j][1]);
            float4 o; o.x = a0.x; o.y = a0.y; o.z = a1.x; o.w = a1.y;
            gq4[(n0 + wg * 4 + j) * 50 + c] = o;
        }
    }
}

// ---------------- K2: fused per-review ABAE, bf16 SMEM tile, occ 4 ------------
#define SM_WORDS 13608

__global__ __launch_bounds__(256, 4)
void mainkern(const int* __restrict__ hist, const float* __restrict__ wemb,
              const float* __restrict__ rneg, const float* __restrict__ Wb,
              const float* __restrict__ Tw) {
    extern __shared__ float sm[];
    int n = blockIdx.x;
    int tid = threadIdx.x, w = tid >> 5, lane = tid & 31;

    // -------- extra block: U_loss (exact fp32 Tw) --------
    if (n == NREV) {
        float* Ts  = sm;          // 6400
        float* nrm = sm + 6400;   // 32
        float* red = sm + 6432;   // 8
        for (int i = tid; i < DW * AASP; i += 256) Ts[i] = Tw[i];
        __syncthreads();
        if (tid < AASP) {
            float s = 0.f;
            for (int d = 0; d < DW; d++) { float v = Ts[d * AASP + tid]; s += v * v; }
            nrm[tid] = fmaxf(sqrtf(s), 1e-12f);
        }
        __syncthreads();
        float part = 0.f;
        for (int pr = tid; pr < AASP * AASP; pr += 256) {
            int a = pr >> 5, b = pr & 31;
            float s = 0.f;
            for (int d = 0; d < DW; d++) s += Ts[d * AASP + a] * Ts[d * AASP + b];
            float g = s / (nrm[a] * nrm[b]);
            float diff = g - ((a == b) ? 1.f : 0.f);
            part += diff * diff;
        }
        float v = warp_sum(part);
        if (lane == 0) red[w] = v;
        __syncthreads();
        if (tid == 0) {
            float t = 0.f;
            for (int k = 0; k < 8; k++) t += red[k];
            g_U[0] = t / (float)(AASP * AASP);
        }
        return;
    }

    uint2* eb2  = (uint2*)sm;
    float* qs   = sm + 12800;
    float* ax   = sm + 13000;
    float* zs   = sm + 13128;
    float* p    = sm + 13328;
    float* part = sm + 13360;
    float* tot  = sm + 13464;
    int*   tok  = (int*)(sm + 13480);

    if (tid < LTOK) tok[tid] = hist[n * LTOK + tid];
    if (tid < DW)   qs[tid]  = g_q[n * DW + tid];
    __syncthreads();

    bool hi = (lane < 18);
    const float4* qs4 = (const float4*)qs;
    float4 qv0 = qs4[lane];
    float4 qv1 = hi ? qs4[32 + lane] : make_float4(0, 0, 0, 0);
    const float4* we4 = (const float4*)wemb;

    // -------- single gather + dx (fp32 exact) + bf16 tile store --------
    #pragma unroll
    for (int t0 = 0; t0 < 16; t0 += 4) {
        float4 v0[4], v1[4];
        #pragma unroll
        for (int t = 0; t < 4; t++) {
            int rb = tok[w * 16 + t0 + t] * 50;
            v0[t] = __ldg(&we4[rb + lane]);
            v1[t] = hi ? __ldg(&we4[rb + 32 + lane]) : make_float4(0, 0, 0, 0);
        }
        float a[4];
        #pragma unroll
        for (int t = 0; t < 4; t++) {
            int l = w * 16 + t0 + t;
            eb2[l * 50 + lane] = pack_bf16x4(v0[t]);
            if (hi) eb2[l * 50 + 32 + lane] = pack_bf16x4(v1[t]);
            a[t] = dot4(v0[t], qv0) + dot4(v1[t], qv1);
        }
        #pragma unroll
        for (int t = 0; t < 4; t++) a[t] = warp_sum(a[t]);
        if (lane == 0) {
            #pragma unroll
            for (int t = 0; t < 4; t++) ax[w * 16 + t0 + t] = a[t];
        }
    }
    __syncthreads();

    // -------- softmax over 128 tokens (warp 0) --------
    if (w == 0) {
        float v0 = ax[lane], v1 = ax[lane + 32], v2 = ax[lane + 64], v3 = ax[lane + 96];
        float m = fmaxf(fmaxf(v0, v1), fmaxf(v2, v3));
        #pragma unroll
        for (int o = 16; o; o >>= 1) m = fmaxf(m, __shfl_xor_sync(0xffffffffu, m, o));
        v0 = __expf(v0 - m); v1 = __expf(v1 - m);
        v2 = __expf(v2 - m); v3 = __expf(v3 - m);
        float s = (v0 + v1) + (v2 + v3);
        #pragma unroll
        for (int o = 16; o; o >>= 1) s += __shfl_xor_sync(0xffffffffu, s, o);
        float inv = 1.f / s;
        ax[lane] = v0 * inv; ax[lane + 32] = v1 * inv;
        ax[lane + 64] = v2 * inv; ax[lane + 96] = v3 * inv;
    }
    __syncthreads();

    // -------- z_s from bf16 SMEM tile (reshape trick, flat slices) --------
    {
        const float4* ax4 = (const float4*)ax;
        float4 av = ax4[lane];
        #pragma unroll
        for (int j0 = 0; j0 < 24; j0 += 4) {
            float a[4];
            #pragma unroll
            for (int k = 0; k < 4; k++) {
                int d = w + 8 * (j0 + k);
                uint2 u = eb2[d * 32 + lane];
                float2 f0 = bf2f(u.x), f1 = bf2f(u.y);
                a[k] = f0.x * av.x + f0.y * av.y + f1.x * av.z + f1.y * av.w;
            }
            #pragma unroll
            for (int k = 0; k < 4; k++) a[k] = warp_sum(a[k]);
            if (lane == 0) {
                #pragma unroll
                for (int k = 0; k < 4; k++) zs[w + 8 * (j0 + k)] = a[k];
            }
        }
        {   // leftover d = 192 + w
            int d = 192 + w;
            uint2 u = eb2[d * 32 + lane];
            float2 f0 = bf2f(u.x), f1 = bf2f(u.y);
            float a = warp_sum(f0.x * av.x + f0.y * av.y + f1.x * av.z + f1.y * av.w);
            if (lane == 0) zs[d] = a;
        }
    }
    __syncthreads();

    // -------- logits = z_s @ W_w^T + W_b (bf16 weights) --------
    {
        const float4* zs4 = (const float4*)zs;
        float4 zv0 = zs4[lane];
        float4 zv1 = hi ? zs4[32 + lane] : make_float4(0, 0, 0, 0);
        const uint2* wb2 = (const uint2*)g_Wwb;   // 4 bf16 per uint2
        #pragma unroll
        for (int j = 0; j < 4; j++) {
            int a = w + 8 * j;
            uint2 u0 = __ldg(&wb2[a * 50 + lane]);
            float2 w0 = bf2f(u0.x), w1 = bf2f(u0.y);
            float acc = w0.x * zv0.x + w0.y * zv0.y + w1.x * zv0.z + w1.y * zv0.w;
            if (hi) {
                uint2 u1 = __ldg(&wb2[a * 50 + 32 + lane]);
                float2 w2 = bf2f(u1.x), w3 = bf2f(u1.y);
                acc += w2.x * zv1.x + w2.y * zv1.y + w3.x * zv1.z + w3.y * zv1.w;
            }
            acc = warp_sum(acc);
            if (lane == 0) p[a] = acc + Wb[a];
        }
    }
    __syncthreads();

    // -------- softmax over A=32 (warp 0) --------
    if (w == 0) {
        float v = p[lane];
        float m = v;
        #pragma unroll
        for (int o = 16; o; o >>= 1) m = fmaxf(m, __shfl_xor_sync(0xffffffffu, m, o));
        float ex = __expf(v - m);
        float s = ex;
        #pragma unroll
        for (int o = 16; o; o >>= 1) s += __shfl_xor_sync(0xffffffffu, s, o);
        p[lane] = ex / s;
    }
    __syncthreads();

    // -------- r_s = p @ T_w^T (bf16 Tw row = 64B = 4 LDG.128) --------
    float rsv = 0.f, zsv = 0.f, ng[NNEG];
    #pragma unroll
    for (int k = 0; k < NNEG; k++) ng[k] = 0.f;
    if (tid < DW) {
        #pragma unroll
        for (int k = 0; k < NNEG; k++)
            ng[k] = __ldg(&rneg[(n * NNEG + k) * DW + tid]);
        const uint4* tb4 = (const uint4*)(g_Twb + tid * AASP);  // 8 bf16 per uint4
        float acc = 0.f;
        #pragma unroll
        for (int j = 0; j < 4; j++) {
            uint4 t = __ldg(&tb4[j]);
            float2 a0 = bf2f(t.x), a1 = bf2f(t.y), a2 = bf2f(t.z), a3 = bf2f(t.w);
            acc += a0.x * p[j * 8 + 0] + a0.y * p[j * 8 + 1]
                 + a1.x * p[j * 8 + 2] + a1.y * p[j * 8 + 3]
                 + a2.x * p[j * 8 + 4] + a2.y * p[j * 8 + 5]
                 + a3.x * p[j * 8 + 6] + a3.y * p[j * 8 + 7];
        }
        g_rs[n * DW + tid] = acc;
        rsv = acc;
        zsv = zs[tid];
    }

    float v[13];
    v[0] = zsv * zsv; v[1] = rsv * rsv; v[2] = zsv * rsv;
    #pragma unroll
    for (int k = 0; k < NNEG; k++) { v[3 + k] = ng[k] * ng[k]; v[8 + k] = ng[k] * rsv; }
    #pragma unroll
    for (int x = 0; x < 13; x++) v[x] = warp_sum(v[x]);
    if (lane == 0) {
        #pragma unroll
        for (int x = 0; x < 13; x++) part[w * 13 + x] = v[x];
    }
    __syncthreads();
    if (w == 0 && lane < 13) {
        float s = 0.f;
        #pragma unroll
        for (int k = 0; k < 8; k++) s += part[k * 13 + lane];
        tot[lane] = s;
    }
    __syncthreads();
    if (tid == 0) {
        float nz = fmaxf(sqrtf(tot[0]), 1e-12f);
        float nr = fmaxf(sqrtf(tot[1]), 1e-12f);
        float c1 = tot[2] / (nz * nr);
        float h = 0.f;
        #pragma unroll
        for (int k = 0; k < NNEG; k++) {
            float c2 = tot[8 + k] / (fmaxf(sqrtf(tot[3 + k]), 1e-12f) * nr);
            h += fmaxf(0.f, c2 - c1);
        }
        g_hinge[n] = h;
    }
}

// ---------------- K3: fused segment means + prediction ------------------------
__global__ __launch_bounds__(256, 8)
void segpred(const int* __restrict__ uhi, const int* __restrict__ usi,
             const int* __restrict__ ihi, const int* __restrict__ isi,
             const float* __restrict__ label, int F) {
    int b = blockIdx.x;
    int tid = threadIdx.x, w = tid >> 5, lane = tid & 31;
    __shared__ int bnd[4];
    __shared__ float red[8];
    if (tid < 2) {
        const int* seg = tid ? isi : usi;
        int lo = 0, hi = F;
        while (lo < hi) { int m = (lo + hi) >> 1; if (seg[m] < b) lo = m + 1; else hi = m; }
        bnd[tid * 2] = lo;
        int lo2 = lo, hi2 = F;
        while (lo2 < hi2) { int m = (lo2 + hi2) >> 1; if (seg[m] < b + 1) lo2 = m + 1; else hi2 = m; }
        bnd[tid * 2 + 1] = lo2;
    }
    __syncthreads();

    float prod = 0.f;
    int d = tid;
    if (d < DW) {
        float um, im;
        {
            int lo = bnd[0], cnt = bnd[1] - bnd[0];
            float s0 = 0.f, s1 = 0.f, s2 = 0.f, s3 = 0.f;
            int j = 0;
            for (; j + 4 <= cnt; j += 4) {
                s0 += g_rs[uhi[lo + j] * DW + d];
                s1 += g_rs[uhi[lo + j + 1] * DW + d];
                s2 += g_rs[uhi[lo + j + 2] * DW + d];
                s3 += g_rs[uhi[lo + j + 3] * DW + d];
            }
            for (; j < cnt; j++) s0 += g_rs[uhi[lo + j] * DW + d];
            um = ((s0 + s1) + (s2 + s3)) / (float)cnt;
        }
        {
            int lo = bnd[2], cnt = bnd[3] - bnd[2];
            float s0 = 0.f, s1 = 0.f, s2 = 0.f, s3 = 0.f;
            int j = 0;
            for (; j + 4 <= cnt; j += 4) {
                s0 += g_rs[ihi[lo + j] * DW + d];
                s1 += g_rs[ihi[lo + j + 1] * DW + d];
                s2 += g_rs[ihi[lo + j + 2] * DW + d];
                s3 += g_rs[ihi[lo + j + 3] * DW + d];
            }
            for (; j < cnt; j++) s0 += g_rs[ihi[lo + j] * DW + d];
            im = ((s0 + s1) + (s2 + s3)) / (float)cnt;
        }
        prod = um * im;
    }
    float s = warp_sum(prod);
    if (lane == 0) red[w] = s;
    __syncthreads();
    if (tid == 0) {
        float t = 0.f;
        #pragma unroll
        for (int k = 0; k < 8; k++) t += red[k];
        float e = t + 3.5f - label[b];
        g_sq[b] = e * e;
    }
}

// ---------------- K4: final reductions ----------------------------------------
__global__ __launch_bounds__(1024, 1)
void finkern(float* __restrict__ out) {
    __shared__ float sc[32];
    int tid = threadIdx.x, w = tid >> 5, lane = tid & 31;

    float s = 0.f;
    for (int i = tid; i < NREV; i += 1024) s += g_hinge[i];
    s = warp_sum(s);
    if (lane == 0) sc[w] = s;
    __syncthreads();
    float hs = 0.f;
    if (tid == 0) for (int k = 0; k < 32; k++) hs += sc[k];
    __syncthreads();

    float s2 = 0.f;
    for (int i = tid; i < BUSR; i += 1024) s2 += g_sq[i];
    s2 = warp_sum(s2);
    if (lane == 0) sc[w] = s2;
    __syncthreads();
    if (tid == 0) {
        float rsum = 0.f;
        for (int k = 0; k < 32; k++) rsum += sc[k];
        float rating = rsum / (float)BUSR;
        float J = hs / (float)(NREV * NNEG);
        float abae = g_U[0] + J;
        out[0] = rating + abae;
        out[1] = rating;
        out[2] = abae;
    }
}

// ---------------- launch ------------------------------------------------------
extern "C" void kernel_launch(void* const* d_in, const int* in_sizes, int n_in,
                              void* d_out, int out_size) {
    const int*   hist  = (const int*)d_in[0];
    const float* rpos  = (const float*)d_in[1];
    const float* rneg  = (const float*)d_in[2];
    const float* label = (const float*)d_in[5];
    const int*   uhi   = (const int*)d_in[6];
    const int*   usi   = (const int*)d_in[7];
    const int*   ihi   = (const int*)d_in[8];
    const int*   isi   = (const int*)d_in[9];
    const float* wemb  = (const float*)d_in[10];
    const float* Mw    = (const float*)d_in[11];
    const float* Ww    = (const float*)d_in[12];
    const float* Wb    = (const float*)d_in[13];
    const float* Tw    = (const float*)d_in[14];
    float* out = (float*)d_out;
    int F = in_sizes[6];

    const int SMEM_QK   = (DW * DW + 32 * DW) * 4;   // 185600 B
    const int SMEM_MAIN = SM_WORDS * 4;              // 54432 B
    cudaFuncSetAttribute(qk, cudaFuncAttributeMaxDynamicSharedMemorySize, SMEM_QK);
    cudaFuncSetAttribute(mainkern, cudaFuncAttributeMaxDynamicSharedMemorySize, SMEM_MAIN);

    wconv<<<(AASP * DW + 255) / 256, 256>>>(Ww, Tw);
    qk<<<NREV / 32, 512, SMEM_QK>>>(rpos, Mw);
    mainkern<<<NREV + 1, 256, SMEM_MAIN>>>(hist, wemb, rneg, Wb, Tw);
    segpred<<<BUSR, 256>>>(uhi, usi, ihi, isi, label, F);
    finkern<<<1, 1024>>>(out);
}

// round 11
// speedup vs baseline: 1.3136x; 1.0468x over previous
#include <cuda_runtime.h>
#include <cuda_bf16.h>
#include <math.h>

#define NREV 4096
#define LTOK 128
#define DW   200
#define AASP 32
#define NNEG 5
#define BUSR 1024

// ---------------- scratch (device globals) -----------------------------------
__device__ __align__(16) float g_q[NREV * DW];
__device__ __align__(16) float g_rs[NREV * DW];
__device__ float g_hinge[NREV];
__device__ float g_sq[BUSR];
__device__ float g_U[1];
__device__ __align__(16) __nv_bfloat16 g_Wwb[AASP * DW];
__device__ __align__(16) __nv_bfloat16 g_Twb[DW * AASP];
__device__ int g_ubnd[BUSR + 1];
__device__ int g_ibnd[BUSR + 1];

__device__ __forceinline__ float dot4(float4 a, float4 b) {
    return a.x * b.x + a.y * b.y + a.z * b.z + a.w * b.w;
}
__device__ __forceinline__ float warp_sum(float v) {
    #pragma unroll
    for (int o = 16; o; o >>= 1) v += __shfl_down_sync(0xffffffffu, v, o);
    return v;
}
__device__ __forceinline__ uint2 pack_bf16x4(float4 v) {
    __nv_bfloat162 a = __float22bfloat162_rn(make_float2(v.x, v.y));
    __nv_bfloat162 b = __float22bfloat162_rn(make_float2(v.z, v.w));
    uint2 u;
    u.x = *(unsigned int*)&a;
    u.y = *(unsigned int*)&b;
    return u;
}
__device__ __forceinline__ float2 bf2f(unsigned int u) {
    return __bfloat1622float2(*(__nv_bfloat162*)&u);
}
// ---- f32x2 packed math (sm_103a) ----
__device__ __forceinline__ unsigned long long pk2(float x, float y) {
    unsigned long long r;
    asm("mov.b64 %0, {%1, %2};" : "=l"(r) : "f"(x), "f"(y));
    return r;
}
__device__ __forceinline__ float2 upk2(unsigned long long v) {
    float2 f;
    asm("mov.b64 {%0, %1}, %2;" : "=f"(f.x), "=f"(f.y) : "l"(v));
    return f;
}
__device__ __forceinline__ unsigned long long fma2(unsigned long long a,
                                                   unsigned long long b,
                                                   unsigned long long c) {
    unsigned long long d;
    asm("fma.rn.f32x2 %0, %1, %2, %3;" : "=l"(d) : "l"(a), "l"(b), "l"(c));
    return d;
}

// ---------------- K0: prep — bf16 weights + segment boundaries ---------------
__global__ __launch_bounds__(256, 4)
void prep(const float* __restrict__ Ww, const float* __restrict__ Tw,
          const int* __restrict__ usi, const int* __restrict__ isi, int F) {
    int i = blockIdx.x * 256 + threadIdx.x;
    if (i < AASP * DW) {
        g_Wwb[i] = __float2bfloat16(Ww[i]);
        g_Twb[i] = __float2bfloat16(Tw[i]);
    }
    if (i < F) {
        int u = usi[i];
        if (i == 0 || usi[i - 1] != u) g_ubnd[u] = i;
        int v = isi[i];
        if (i == 0 || isi[i - 1] != v) g_ibnd[v] = i;
    }
    if (i == 0) { g_ubnd[BUSR] = F; g_ibnd[BUSR] = F; }
}

// ---------------- K1: q = rev_pos @ M_w --------------------------------------
__global__ __launch_bounds__(512, 1)
void qk(const float* __restrict__ rp, const float* __restrict__ Mw) {
    extern __shared__ float sm[];
    float* Ms  = sm;            // 40000
    float* rps = sm + DW * DW;  // 6400
    int tid = threadIdx.x, w = tid >> 5, lane = tid & 31;
    {
        const float4* Mw4 = (const float4*)Mw;
        float4* Ms4w = (float4*)Ms;
        for (int i = tid; i < DW * DW / 4; i += 512) Ms4w[i] = __ldg(&Mw4[i]);
        int n0 = blockIdx.x * 32;
        const float4* rp4 = (const float4*)(rp + n0 * DW);
        float4* rps4w = (float4*)rps;
        for (int i = tid; i < 32 * DW / 4; i += 512) rps4w[i] = __ldg(&rp4[i]);
    }
    __syncthreads();

    int wg = w & 7;
    int h  = w >> 3;
    bool act = (h == 0) || (lane < 18);
    int c = h ? (32 + (lane < 18 ? lane : 0)) : lane;

    const float4* Ms4  = (const float4*)Ms;
    const float4* rps4 = (const float4*)rps;

    unsigned long long acc[4][2];
    #pragma unroll
    for (int j = 0; j < 4; j++) { acc[j][0] = 0ull; acc[j][1] = 0ull; }

    for (int d2b = 0; d2b < 50; d2b++) {
        float4 r4[4];
        #pragma unroll
        for (int j = 0; j < 4; j++) r4[j] = rps4[(wg * 4 + j) * 50 + d2b];
        #pragma unroll
        for (int s = 0; s < 4; s++) {
            float4 m = Ms4[(d2b * 4 + s) * 50 + c];
            unsigned long long m01 = pk2(m.x, m.y), m23 = pk2(m.z, m.w);
            #pragma unroll
            for (int j = 0; j < 4; j++) {
                float r = (s == 0) ? r4[j].x : (s == 1) ? r4[j].y
                        : (s == 2) ? r4[j].z : r4[j].w;
                unsigned long long rr = pk2(r, r);
                acc[j][0] = fma2(rr, m01, acc[j][0]);
                acc[j][1] = fma2(rr, m23, acc[j][1]);
            }
        }
    }

    if (act) {
        int n0 = blockIdx.x * 32;
        float4* gq4 = (float4*)g_q;
        #pragma unroll
        for (int j = 0; j < 4; j++) {
            float2 a0 = upk2(acc[j][0]), a1 = upk2(acc[j][1]);
            float4 o; o.x = a0.x; o.y = a0.y; o.z = a1.x; o.w = a1.y;
            gq4[(n0 + wg * 4 + j) * 50 + c] = o;
        }
    }
}

// ---------------- K2: fused per-review ABAE, bf16 SMEM tile, occ 4 ------------
#define SM_WORDS 13608

__global__ __launch_bounds__(256, 4)
void mainkern(const int* __restrict__ hist, const float* __restrict__ wemb,
              const float* __restrict__ rneg, const float* __restrict__ Wb,
              const float* __restrict__ Tw) {
    extern __shared__ float sm[];
    int n = blockIdx.x;
    int tid = threadIdx.x, w = tid >> 5, lane = tid & 31;

    // -------- extra block: U_loss (exact fp32 Tw) --------
    if (n == NREV) {
        float* Ts  = sm;          // 6400
        float* nrm = sm + 6400;   // 32
        float* red = sm + 6432;   // 8
        for (int i = tid; i < DW * AASP; i += 256) Ts[i] = Tw[i];
        __syncthreads();
        if (tid < AASP) {
            float s = 0.f;
            for (int d = 0; d < DW; d++) { float v = Ts[d * AASP + tid]; s += v * v; }
            nrm[tid] = fmaxf(sqrtf(s), 1e-12f);
        }
        __syncthreads();
        float part = 0.f;
        for (int pr = tid; pr < AASP * AASP; pr += 256) {
            int a = pr >> 5, b = pr & 31;
            float s = 0.f;
            for (int d = 0; d < DW; d++) s += Ts[d * AASP + a] * Ts[d * AASP + b];
            float g = s / (nrm[a] * nrm[b]);
            float diff = g - ((a == b) ? 1.f : 0.f);
            part += diff * diff;
        }
        float v = warp_sum(part);
        if (lane == 0) red[w] = v;
        __syncthreads();
        if (tid == 0) {
            float t = 0.f;
            for (int k = 0; k < 8; k++) t += red[k];
            g_U[0] = t / (float)(AASP * AASP);
        }
        return;
    }

    uint2* eb2  = (uint2*)sm;
    float* qs   = sm + 12800;
    float* ax   = sm + 13000;
    float* zs   = sm + 13128;
    float* p    = sm + 13328;
    float* part = sm + 13360;
    float* tot  = sm + 13464;
    int*   tok  = (int*)(sm + 13480);

    if (tid < LTOK) tok[tid] = hist[n * LTOK + tid];
    if (tid < DW)   qs[tid]  = g_q[n * DW + tid];
    __syncthreads();

    bool hi = (lane < 18);
    const float4* qs4 = (const float4*)qs;
    float4 qv0 = qs4[lane];
    float4 qv1 = hi ? qs4[32 + lane] : make_float4(0, 0, 0, 0);
    const float4* we4 = (const float4*)wemb;

    // -------- single gather + dx (fp32 exact) + bf16 tile store --------
    #pragma unroll
    for (int t0 = 0; t0 < 16; t0 += 4) {
        float4 v0[4], v1[4];
        #pragma unroll
        for (int t = 0; t < 4; t++) {
            int rb = tok[w * 16 + t0 + t] * 50;
            v0[t] = __ldg(&we4[rb + lane]);
            v1[t] = hi ? __ldg(&we4[rb + 32 + lane]) : make_float4(0, 0, 0, 0);
        }
        float a[4];
        #pragma unroll
        for (int t = 0; t < 4; t++) {
            int l = w * 16 + t0 + t;
            eb2[l * 50 + lane] = pack_bf16x4(v0[t]);
            if (hi) eb2[l * 50 + 32 + lane] = pack_bf16x4(v1[t]);
            a[t] = dot4(v0[t], qv0) + dot4(v1[t], qv1);
        }
        #pragma unroll
        for (int t = 0; t < 4; t++) a[t] = warp_sum(a[t]);
        if (lane == 0) {
            #pragma unroll
            for (int t = 0; t < 4; t++) ax[w * 16 + t0 + t] = a[t];
        }
    }
    __syncthreads();

    // -------- softmax over 128 tokens (warp 0) --------
    if (w == 0) {
        float v0 = ax[lane], v1 = ax[lane + 32], v2 = ax[lane + 64], v3 = ax[lane + 96];
        float m = fmaxf(fmaxf(v0, v1), fmaxf(v2, v3));
        #pragma unroll
        for (int o = 16; o; o >>= 1) m = fmaxf(m, __shfl_xor_sync(0xffffffffu, m, o));
        v0 = __expf(v0 - m); v1 = __expf(v1 - m);
        v2 = __expf(v2 - m); v3 = __expf(v3 - m);
        float s = (v0 + v1) + (v2 + v3);
        #pragma unroll
        for (int o = 16; o; o >>= 1) s += __shfl_xor_sync(0xffffffffu, s, o);
        float inv = 1.f / s;
        ax[lane] = v0 * inv; ax[lane + 32] = v1 * inv;
        ax[lane + 64] = v2 * inv; ax[lane + 96] = v3 * inv;
    }
    __syncthreads();

    // -------- z_s from bf16 SMEM tile (reshape trick, flat slices) --------
    {
        const float4* ax4 = (const float4*)ax;
        float4 av = ax4[lane];
        #pragma unroll
        for (int j0 = 0; j0 < 24; j0 += 4) {
            float a[4];
            #pragma unroll
            for (int k = 0; k < 4; k++) {
                int d = w + 8 * (j0 + k);
                uint2 u = eb2[d * 32 + lane];
                float2 f0 = bf2f(u.x), f1 = bf2f(u.y);
                a[k] = f0.x * av.x + f0.y * av.y + f1.x * av.z + f1.y * av.w;
            }
            #pragma unroll
            for (int k = 0; k < 4; k++) a[k] = warp_sum(a[k]);
            if (lane == 0) {
                #pragma unroll
                for (int k = 0; k < 4; k++) zs[w + 8 * (j0 + k)] = a[k];
            }
        }
        {   // leftover d = 192 + w
            int d = 192 + w;
            uint2 u = eb2[d * 32 + lane];
            float2 f0 = bf2f(u.x), f1 = bf2f(u.y);
            float a = warp_sum(f0.x * av.x + f0.y * av.y + f1.x * av.z + f1.y * av.w);
            if (lane == 0) zs[d] = a;
        }
    }
    __syncthreads();

    // -------- logits = z_s @ W_w^T + W_b (bf16 weights) --------
    {
        const float4* zs4 = (const float4*)zs;
        float4 zv0 = zs4[lane];
        float4 zv1 = hi ? zs4[32 + lane] : make_float4(0, 0, 0, 0);
        const uint2* wb2 = (const uint2*)g_Wwb;
        #pragma unroll
        for (int j = 0; j < 4; j++) {
            int a = w + 8 * j;
            uint2 u0 = __ldg(&wb2[a * 50 + lane]);
            float2 w0 = bf2f(u0.x), w1 = bf2f(u0.y);
            float acc = w0.x * zv0.x + w0.y * zv0.y + w1.x * zv0.z + w1.y * zv0.w;
            if (hi) {
                uint2 u1 = __ldg(&wb2[a * 50 + 32 + lane]);
                float2 w2 = bf2f(u1.x), w3 = bf2f(u1.y);
                acc += w2.x * zv1.x + w2.y * zv1.y + w3.x * zv1.z + w3.y * zv1.w;
            }
            acc = warp_sum(acc);
            if (lane == 0) p[a] = acc + Wb[a];
        }
    }
    __syncthreads();

    // -------- softmax over A=32 (warp 0) --------
    if (w == 0) {
        float v = p[lane];
        float m = v;
        #pragma unroll
        for (int o = 16; o; o >>= 1) m = fmaxf(m, __shfl_xor_sync(0xffffffffu, m, o));
        float ex = __expf(v - m);
        float s = ex;
        #pragma unroll
        for (int o = 16; o; o >>= 1) s += __shfl_xor_sync(0xffffffffu, s, o);
        p[lane] = ex / s;
    }
    __syncthreads();

    // -------- r_s = p @ T_w^T (bf16 Tw row) ; 13 fused dots --------
    float rsv = 0.f, zsv = 0.f, ng[NNEG];
    #pragma unroll
    for (int k = 0; k < NNEG; k++) ng[k] = 0.f;
    if (tid < DW) {
        #pragma unroll
        for (int k = 0; k < NNEG; k++)
            ng[k] = __ldg(&rneg[(n * NNEG + k) * DW + tid]);
        const uint4* tb4 = (const uint4*)(g_Twb + tid * AASP);
        float acc = 0.f;
        #pragma unroll
        for (int j = 0; j < 4; j++) {
            uint4 t = __ldg(&tb4[j]);
            float2 a0 = bf2f(t.x), a1 = bf2f(t.y), a2 = bf2f(t.z), a3 = bf2f(t.w);
            acc += a0.x * p[j * 8 + 0] + a0.y * p[j * 8 + 1]
                 + a1.x * p[j * 8 + 2] + a1.y * p[j * 8 + 3]
                 + a2.x * p[j * 8 + 4] + a2.y * p[j * 8 + 5]
                 + a3.x * p[j * 8 + 6] + a3.y * p[j * 8 + 7];
        }
        g_rs[n * DW + tid] = acc;
        rsv = acc;
        zsv = zs[tid];
    }

    float v[13];
    v[0] = zsv * zsv; v[1] = rsv * rsv; v[2] = zsv * rsv;
    #pragma unroll
    for (int k = 0; k < NNEG; k++) { v[3 + k] = ng[k] * ng[k]; v[8 + k] = ng[k] * rsv; }
    #pragma unroll
    for (int x = 0; x < 13; x++) v[x] = warp_sum(v[x]);
    if (lane == 0) {
        #pragma unroll
        for (int x = 0; x < 13; x++) part[w * 13 + x] = v[x];
    }
    __syncthreads();
    if (w == 0 && lane < 13) {
        float s = 0.f;
        #pragma unroll
        for (int k = 0; k < 8; k++) s += part[k * 13 + lane];
        tot[lane] = s;
    }
    __syncthreads();
    if (tid == 0) {
        float nz = fmaxf(sqrtf(tot[0]), 1e-12f);
        float nr = fmaxf(sqrtf(tot[1]), 1e-12f);
        float c1 = tot[2] / (nz * nr);
        float h = 0.f;
        #pragma unroll
        for (int k = 0; k < NNEG; k++) {
            float c2 = tot[8 + k] / (fmaxf(sqrtf(tot[3 + k]), 1e-12f) * nr);
            h += fmaxf(0.f, c2 - c1);
        }
        g_hinge[n] = h;
    }
}

// ---------------- K3: segment means + prediction (no binary search) -----------
__global__ __launch_bounds__(256, 8)
void segpred(const int* __restrict__ uhi, const int* __restrict__ ihi,
             const float* __restrict__ label) {
    int b = blockIdx.x;
    int tid = threadIdx.x, w = tid >> 5, lane = tid & 31;
    __shared__ int sidx[96];      // [0:48) u, [48:96) i
    __shared__ int meta[4];       // cu, ci, lou, loi
    __shared__ float red[8];

    if (w < 2) {
        const int* bnd = w ? g_ibnd : g_ubnd;
        const int* idx = w ? ihi : uhi;
        int lo = bnd[b], hi2 = bnd[b + 1];
        int cnt = hi2 - lo;
        if (lane == 0) { meta[w] = cnt; meta[2 + w] = lo; }
        for (int j = lane; j < cnt && j < 48; j += 32)
            sidx[w * 48 + j] = idx[lo + j];
    }
    __syncthreads();

    int cu = meta[0], ci = meta[1];
    float prod = 0.f;
    int d = tid;
    if (d < DW) {
        float u0 = 0.f, u1 = 0.f, u2 = 0.f, u3 = 0.f;
        float i0 = 0.f, i1 = 0.f, i2 = 0.f, i3 = 0.f;
        int cuc = cu < 48 ? cu : 48;
        int cic = ci < 48 ? ci : 48;
        int c = cuc < cic ? cuc : cic;
        int j = 0;
        for (; j + 4 <= c; j += 4) {   // interleaved: 8 loads in flight
            u0 += g_rs[sidx[j]      * DW + d];
            i0 += g_rs[sidx[48 + j] * DW + d];
            u1 += g_rs[sidx[j + 1]      * DW + d];
            i1 += g_rs[sidx[48 + j + 1] * DW + d];
            u2 += g_rs[sidx[j + 2]      * DW + d];
            i2 += g_rs[sidx[48 + j + 2] * DW + d];
            u3 += g_rs[sidx[j + 3]      * DW + d];
            i3 += g_rs[sidx[48 + j + 3] * DW + d];
        }
        for (int k = j; k < cuc; k++) u0 += g_rs[sidx[k] * DW + d];
        for (int k = j; k < cic; k++) i0 += g_rs[sidx[48 + k] * DW + d];
        for (int k = 48; k < cu; k++) u0 += g_rs[uhi[meta[2] + k] * DW + d];
        for (int k = 48; k < ci; k++) i0 += g_rs[ihi[meta[3] + k] * DW + d];
        float um = ((u0 + u1) + (u2 + u3)) / (float)cu;
        float im = ((i0 + i1) + (i2 + i3)) / (float)ci;
        prod = um * im;
    }
    float s = warp_sum(prod);
    if (lane == 0) red[w] = s;
    __syncthreads();
    if (tid == 0) {
        float t = 0.f;
        #pragma unroll
        for (int k = 0; k < 8; k++) t += red[k];
        float e = t + 3.5f - label[b];
        g_sq[b] = e * e;
    }
}

// ---------------- K4: final reductions (float4, warp-final) -------------------
__global__ __launch_bounds__(1024, 1)
void finkern(float* __restrict__ out) {
    __shared__ float sc[64];
    int tid = threadIdx.x, w = tid >> 5, lane = tid & 31;

    const float4* h4 = (const float4*)g_hinge;   // 1024 float4
    float4 hv = h4[tid];
    float s = (hv.x + hv.y) + (hv.z + hv.w);
    s = warp_sum(s);
    if (lane == 0) sc[w] = s;

    float q = 0.f;
    if (tid < 256) {
        float4 qv = ((const float4*)g_sq)[tid];
        q = (qv.x + qv.y) + (qv.z + qv.w);
    }
    q = warp_sum(q);
    if (lane == 0) sc[32 + w] = q;
    __syncthreads();

    if (w == 0) {
        float hs = warp_sum(sc[lane]);
        float rsum = warp_sum(sc[32 + lane]);
        if (lane == 0) {
            float rating = rsum / (float)BUSR;
            float J = hs / (float)(NREV * NNEG);
            float abae = g_U[0] + J;
            out[0] = rating + abae;
            out[1] = rating;
            out[2] = abae;
        }
    }
}

// ---------------- launch ------------------------------------------------------
extern "C" void kernel_launch(void* const* d_in, const int* in_sizes, int n_in,
                              void* d_out, int out_size) {
    const int*   hist  = (const int*)d_in[0];
    const float* rpos  = (const float*)d_in[1];
    const float* rneg  = (const float*)d_in[2];
    const float* label = (const float*)d_in[5];
    const int*   uhi   = (const int*)d_in[6];
    const int*   usi   = (const int*)d_in[7];
    const int*   ihi   = (const int*)d_in[8];
    const int*   isi   = (const int*)d_in[9];
    const float* wemb  = (const float*)d_in[10];
    const float* Mw    = (const float*)d_in[11];
    const float* Ww    = (const float*)d_in[12];
    const float* Wb    = (const float*)d_in[13];
    const float* Tw    = (const float*)d_in[14];
    float* out = (float*)d_out;
    int F = in_sizes[6];

    const int SMEM_QK   = (DW * DW + 32 * DW) * 4;   // 185600 B
    const int SMEM_MAIN = SM_WORDS * 4;              // 54432 B
    cudaFuncSetAttribute(qk, cudaFuncAttributeMaxDynamicSharedMemorySize, SMEM_QK);
    cudaFuncSetAttribute(mainkern, cudaFuncAttributeMaxDynamicSharedMemorySize, SMEM_MAIN);

    int prep_n = (AASP * DW > F) ? AASP * DW : F;
    prep<<<(prep_n + 255) / 256, 256>>>(Ww, Tw, usi, isi, F);
    qk<<<NREV / 32, 512, SMEM_QK>>>(rpos, Mw);
    mainkern<<<NREV + 1, 256, SMEM_MAIN>>>(hist, wemb, rneg, Wb, Tw);
    segpred<<<BUSR, 256>>>(uhi, ihi, label);
    finkern<<<1, 1024>>>(out);
}

// round 12
// speedup vs baseline: 1.3385x; 1.0189x over previous
#include <cuda_runtime.h>
#include <cuda_bf16.h>
#include <math.h>

#define NREV 4096
#define LTOK 128
#define DW   200
#define AASP 32
#define NNEG 5
#define BUSR 1024

// ---------------- scratch (device globals) -----------------------------------
__device__ __align__(16) float g_q[NREV * DW];
__device__ __align__(16) float g_rs[NREV * DW];
__device__ __align__(16) float g_hinge[NREV];
__device__ __align__(16) float g_sq[BUSR];
__device__ float g_U[1];
__device__ __align__(16) __nv_bfloat16 g_Wwb[AASP * DW];
__device__ __align__(16) __nv_bfloat16 g_Twb[DW * AASP];
__device__ int g_ubnd[BUSR + 1];
__device__ int g_ibnd[BUSR + 1];
__device__ unsigned int g_cnt;

__device__ __forceinline__ float dot4(float4 a, float4 b) {
    return a.x * b.x + a.y * b.y + a.z * b.z + a.w * b.w;
}
__device__ __forceinline__ float warp_sum(float v) {
    #pragma unroll
    for (int o = 16; o; o >>= 1) v += __shfl_down_sync(0xffffffffu, v, o);
    return v;
}
__device__ __forceinline__ uint2 pack_bf16x4(float4 v) {
    __nv_bfloat162 a = __float22bfloat162_rn(make_float2(v.x, v.y));
    __nv_bfloat162 b = __float22bfloat162_rn(make_float2(v.z, v.w));
    uint2 u;
    u.x = *(unsigned int*)&a;
    u.y = *(unsigned int*)&b;
    return u;
}
__device__ __forceinline__ float2 bf2f(unsigned int u) {
    return __bfloat1622float2(*(__nv_bfloat162*)&u);
}
// ---- f32x2 packed math (sm_103a) ----
__device__ __forceinline__ unsigned long long pk2(float x, float y) {
    unsigned long long r;
    asm("mov.b64 %0, {%1, %2};" : "=l"(r) : "f"(x), "f"(y));
    return r;
}
__device__ __forceinline__ float2 upk2(unsigned long long v) {
    float2 f;
    asm("mov.b64 {%0, %1}, %2;" : "=f"(f.x), "=f"(f.y) : "l"(v));
    return f;
}
__device__ __forceinline__ unsigned long long fma2(unsigned long long a,
                                                   unsigned long long b,
                                                   unsigned long long c) {
    unsigned long long d;
    asm("fma.rn.f32x2 %0, %1, %2, %3;" : "=l"(d) : "l"(a), "l"(b), "l"(c));
    return d;
}

#define QK_BLOCKS (NREV / 32)

// ---------------- K1: q = rev_pos @ M_w  (+ fused prep blocks) ----------------
__global__ __launch_bounds__(512, 1)
void qk(const float* __restrict__ rp, const float* __restrict__ Mw,
        const float* __restrict__ Ww, const float* __restrict__ Tw,
        const int* __restrict__ usi, const int* __restrict__ isi, int F) {
    int tid = threadIdx.x, w = tid >> 5, lane = tid & 31;

    // -------- prep blocks: bf16 weights + segment boundaries --------
    if (blockIdx.x >= QK_BLOCKS) {
        int i = (blockIdx.x - QK_BLOCKS) * 512 + tid;
        if (i < AASP * DW) {
            g_Wwb[i] = __float2bfloat16(Ww[i]);
            g_Twb[i] = __float2bfloat16(Tw[i]);
        }
        if (i < F) {
            int u = usi[i];
            if (i == 0 || usi[i - 1] != u) g_ubnd[u] = i;
            int v = isi[i];
            if (i == 0 || isi[i - 1] != v) g_ibnd[v] = i;
        }
        if (i == 0) { g_ubnd[BUSR] = F; g_ibnd[BUSR] = F; }
        return;
    }

    extern __shared__ float sm[];
    float* Ms  = sm;            // 40000
    float* rps = sm + DW * DW;  // 6400
    {
        const float4* Mw4 = (const float4*)Mw;
        float4* Ms4w = (float4*)Ms;
        for (int i = tid; i < DW * DW / 4; i += 512) Ms4w[i] = __ldg(&Mw4[i]);
        int n0 = blockIdx.x * 32;
        const float4* rp4 = (const float4*)(rp + n0 * DW);
        float4* rps4w = (float4*)rps;
        for (int i = tid; i < 32 * DW / 4; i += 512) rps4w[i] = __ldg(&rp4[i]);
    }
    __syncthreads();

    int wg = w & 7;
    int h  = w >> 3;
    bool act = (h == 0) || (lane < 18);
    int c = h ? (32 + (lane < 18 ? lane : 0)) : lane;

    const float4* Ms4  = (const float4*)Ms;
    const float4* rps4 = (const float4*)rps;

    unsigned long long acc[4][2];
    #pragma unroll
    for (int j = 0; j < 4; j++) { acc[j][0] = 0ull; acc[j][1] = 0ull; }

    for (int d2b = 0; d2b < 50; d2b++) {
        float4 r4[4];
        #pragma unroll
        for (int j = 0; j < 4; j++) r4[j] = rps4[(wg * 4 + j) * 50 + d2b];
        #pragma unroll
        for (int s = 0; s < 4; s++) {
            float4 m = Ms4[(d2b * 4 + s) * 50 + c];
            unsigned long long m01 = pk2(m.x, m.y), m23 = pk2(m.z, m.w);
            #pragma unroll
            for (int j = 0; j < 4; j++) {
                float r = (s == 0) ? r4[j].x : (s == 1) ? r4[j].y
                        : (s == 2) ? r4[j].z : r4[j].w;
                unsigned long long rr = pk2(r, r);
                acc[j][0] = fma2(rr, m01, acc[j][0]);
                acc[j][1] = fma2(rr, m23, acc[j][1]);
            }
        }
    }

    if (act) {
        int n0 = blockIdx.x * 32;
        float4* gq4 = (float4*)g_q;
        #pragma unroll
        for (int j = 0; j < 4; j++) {
            float2 a0 = upk2(acc[j][0]), a1 = upk2(acc[j][1]);
            float4 o; o.x = a0.x; o.y = a0.y; o.z = a1.x; o.w = a1.y;
            gq4[(n0 + wg * 4 + j) * 50 + c] = o;
        }
    }
}

// ---------------- K2: fused per-review ABAE, bf16 SMEM tile, occ 4 ------------
#define SM_WORDS 13608

__global__ __launch_bounds__(256, 4)
void mainkern(const int* __restrict__ hist, const float* __restrict__ wemb,
              const float* __restrict__ rneg, const float* __restrict__ Wb,
              const float* __restrict__ Tw) {
    extern __shared__ float sm[];
    int n = blockIdx.x;
    int tid = threadIdx.x, w = tid >> 5, lane = tid & 31;

    // -------- extra block: U_loss (exact fp32 Tw) --------
    if (n == NREV) {
        float* Ts  = sm;          // 6400
        float* nrm = sm + 6400;   // 32
        float* red = sm + 6432;   // 8
        for (int i = tid; i < DW * AASP; i += 256) Ts[i] = Tw[i];
        __syncthreads();
        if (tid < AASP) {
            float s = 0.f;
            for (int d = 0; d < DW; d++) { float v = Ts[d * AASP + tid]; s += v * v; }
            nrm[tid] = fmaxf(sqrtf(s), 1e-12f);
        }
        __syncthreads();
        float part = 0.f;
        for (int pr = tid; pr < AASP * AASP; pr += 256) {
            int a = pr >> 5, b = pr & 31;
            float s = 0.f;
            for (int d = 0; d < DW; d++) s += Ts[d * AASP + a] * Ts[d * AASP + b];
            float g = s / (nrm[a] * nrm[b]);
            float diff = g - ((a == b) ? 1.f : 0.f);
            part += diff * diff;
        }
        float v = warp_sum(part);
        if (lane == 0) red[w] = v;
        __syncthreads();
        if (tid == 0) {
            float t = 0.f;
            for (int k = 0; k < 8; k++) t += red[k];
            g_U[0] = t / (float)(AASP * AASP);
        }
        return;
    }

    uint2* eb2  = (uint2*)sm;
    float* qs   = sm + 12800;
    float* ax   = sm + 13000;
    float* zs   = sm + 13128;
    float* p    = sm + 13328;
    float* part = sm + 13360;
    float* tot  = sm + 13464;
    int*   tok  = (int*)(sm + 13480);

    if (tid < LTOK) tok[tid] = hist[n * LTOK + tid];
    if (tid < DW)   qs[tid]  = g_q[n * DW + tid];
    __syncthreads();

    bool hi = (lane < 18);
    const float4* qs4 = (const float4*)qs;
    float4 qv0 = qs4[lane];
    float4 qv1 = hi ? qs4[32 + lane] : make_float4(0, 0, 0, 0);
    const float4* we4 = (const float4*)wemb;

    // -------- single gather + dx (fp32 exact) + bf16 tile store --------
    #pragma unroll
    for (int t0 = 0; t0 < 16; t0 += 4) {
        float4 v0[4], v1[4];
        #pragma unroll
        for (int t = 0; t < 4; t++) {
            int rb = tok[w * 16 + t0 + t] * 50;
            v0[t] = __ldg(&we4[rb + lane]);
            v1[t] = hi ? __ldg(&we4[rb + 32 + lane]) : make_float4(0, 0, 0, 0);
        }
        float a[4];
        #pragma unroll
        for (int t = 0; t < 4; t++) {
            int l = w * 16 + t0 + t;
            eb2[l * 50 + lane] = pack_bf16x4(v0[t]);
            if (hi) eb2[l * 50 + 32 + lane] = pack_bf16x4(v1[t]);
            a[t] = dot4(v0[t], qv0) + dot4(v1[t], qv1);
        }
        #pragma unroll
        for (int t = 0; t < 4; t++) a[t] = warp_sum(a[t]);
        if (lane == 0) {
            #pragma unroll
            for (int t = 0; t < 4; t++) ax[w * 16 + t0 + t] = a[t];
        }
    }
    __syncthreads();

    // -------- softmax over 128 tokens (warp 0) --------
    if (w == 0) {
        float v0 = ax[lane], v1 = ax[lane + 32], v2 = ax[lane + 64], v3 = ax[lane + 96];
        float m = fmaxf(fmaxf(v0, v1), fmaxf(v2, v3));
        #pragma unroll
        for (int o = 16; o; o >>= 1) m = fmaxf(m, __shfl_xor_sync(0xffffffffu, m, o));
        v0 = __expf(v0 - m); v1 = __expf(v1 - m);
        v2 = __expf(v2 - m); v3 = __expf(v3 - m);
        float s = (v0 + v1) + (v2 + v3);
        #pragma unroll
        for (int o = 16; o; o >>= 1) s += __shfl_xor_sync(0xffffffffu, s, o);
        float inv = 1.f / s;
        ax[lane] = v0 * inv; ax[lane + 32] = v1 * inv;
        ax[lane + 64] = v2 * inv; ax[lane + 96] = v3 * inv;
    }
    __syncthreads();

    // -------- z_s from bf16 SMEM tile (reshape trick, flat slices) --------
    {
        const float4* ax4 = (const float4*)ax;
        float4 av = ax4[lane];
        #pragma unroll
        for (int j0 = 0; j0 < 24; j0 += 4) {
            float a[4];
            #pragma unroll
            for (int k = 0; k < 4; k++) {
                int d = w + 8 * (j0 + k);
                uint2 u = eb2[d * 32 + lane];
                float2 f0 = bf2f(u.x), f1 = bf2f(u.y);
                a[k] = f0.x * av.x + f0.y * av.y + f1.x * av.z + f1.y * av.w;
            }
            #pragma unroll
            for (int k = 0; k < 4; k++) a[k] = warp_sum(a[k]);
            if (lane == 0) {
                #pragma unroll
                for (int k = 0; k < 4; k++) zs[w + 8 * (j0 + k)] = a[k];
            }
        }
        {   // leftover d = 192 + w
            int d = 192 + w;
            uint2 u = eb2[d * 32 + lane];
            float2 f0 = bf2f(u.x), f1 = bf2f(u.y);
            float a = warp_sum(f0.x * av.x + f0.y * av.y + f1.x * av.z + f1.y * av.w);
            if (lane == 0) zs[d] = a;
        }
    }
    __syncthreads();

    // -------- prefetch negatives (consumed in final phase, ~2 phases later) --
    float ng[NNEG];
    #pragma unroll
    for (int k = 0; k < NNEG; k++)
        ng[k] = (tid < DW) ? __ldg(&rneg[(n * NNEG + k) * DW + tid]) : 0.f;

    // -------- logits = z_s @ W_w^T + W_b (bf16 weights) --------
    {
        const float4* zs4 = (const float4*)zs;
        float4 zv0 = zs4[lane];
        float4 zv1 = hi ? zs4[32 + lane] : make_float4(0, 0, 0, 0);
        const uint2* wb2 = (const uint2*)g_Wwb;
        #pragma unroll
        for (int j = 0; j < 4; j++) {
            int a = w + 8 * j;
            uint2 u0 = __ldg(&wb2[a * 50 + lane]);
            float2 w0 = bf2f(u0.x), w1 = bf2f(u0.y);
            float acc = w0.x * zv0.x + w0.y * zv0.y + w1.x * zv0.z + w1.y * zv0.w;
            if (hi) {
                uint2 u1 = __ldg(&wb2[a * 50 + 32 + lane]);
                float2 w2 = bf2f(u1.x), w3 = bf2f(u1.y);
                acc += w2.x * zv1.x + w2.y * zv1.y + w3.x * zv1.z + w3.y * zv1.w;
            }
            acc = warp_sum(acc);
            if (lane == 0) p[a] = acc + Wb[a];
        }
    }
    __syncthreads();

    // -------- softmax over A=32 (warp 0) --------
    if (w == 0) {
        float v = p[lane];
        float m = v;
        #pragma unroll
        for (int o = 16; o; o >>= 1) m = fmaxf(m, __shfl_xor_sync(0xffffffffu, m, o));
        float ex = __expf(v - m);
        float s = ex;
        #pragma unroll
        for (int o = 16; o; o >>= 1) s += __shfl_xor_sync(0xffffffffu, s, o);
        p[lane] = ex / s;
    }
    __syncthreads();

    // -------- r_s = p @ T_w^T (bf16 Tw row) ; 13 fused dots --------
    float rsv = 0.f, zsv = 0.f;
    if (tid < DW) {
        const uint4* tb4 = (const uint4*)(g_Twb + tid * AASP);
        float acc = 0.f;
        #pragma unroll
        for (int j = 0; j < 4; j++) {
            uint4 t = __ldg(&tb4[j]);
            float2 a0 = bf2f(t.x), a1 = bf2f(t.y), a2 = bf2f(t.z), a3 = bf2f(t.w);
            acc += a0.x * p[j * 8 + 0] + a0.y * p[j * 8 + 1]
                 + a1.x * p[j * 8 + 2] + a1.y * p[j * 8 + 3]
                 + a2.x * p[j * 8 + 4] + a2.y * p[j * 8 + 5]
                 + a3.x * p[j * 8 + 6] + a3.y * p[j * 8 + 7];
        }
        g_rs[n * DW + tid] = acc;
        rsv = acc;
        zsv = zs[tid];
    }

    float v[13];
    v[0] = zsv * zsv; v[1] = rsv * rsv; v[2] = zsv * rsv;
    #pragma unroll
    for (int k = 0; k < NNEG; k++) { v[3 + k] = ng[k] * ng[k]; v[8 + k] = ng[k] * rsv; }
    #pragma unroll
    for (int x = 0; x < 13; x++) v[x] = warp_sum(v[x]);
    if (lane == 0) {
        #pragma unroll
        for (int x = 0; x < 13; x++) part[w * 13 + x] = v[x];
    }
    __syncthreads();
    if (w == 0 && lane < 13) {
        float s = 0.f;
        #pragma unroll
        for (int k = 0; k < 8; k++) s += part[k * 13 + lane];
        tot[lane] = s;
    }
    __syncthreads();
    if (tid == 0) {
        float nz = fmaxf(sqrtf(tot[0]), 1e-12f);
        float nr = fmaxf(sqrtf(tot[1]), 1e-12f);
        float c1 = tot[2] / (nz * nr);
        float h = 0.f;
        #pragma unroll
        for (int k = 0; k < NNEG; k++) {
            float c2 = tot[8 + k] / (fmaxf(sqrtf(tot[3 + k]), 1e-12f) * nr);
            h += fmaxf(0.f, c2 - c1);
        }
        g_hinge[n] = h;
    }
}

// ---------------- K3: segment means + prediction + final reduce ---------------
__global__ __launch_bounds__(256, 8)
void segpred(const int* __restrict__ uhi, const int* __restrict__ ihi,
             const float* __restrict__ label, float* __restrict__ out) {
    int b = blockIdx.x;
    int tid = threadIdx.x, w = tid >> 5, lane = tid & 31;
    __shared__ int sidx[96];      // [0:48) u, [48:96) i
    __shared__ int meta[4];       // cu, ci, lou, loi
    __shared__ float red[8];
    __shared__ unsigned int rank;

    if (w < 2) {
        const int* bnd = w ? g_ibnd : g_ubnd;
        const int* idx = w ? ihi : uhi;
        int lo = bnd[b], hi2 = bnd[b + 1];
        int cnt = hi2 - lo;
        if (lane == 0) { meta[w] = cnt; meta[2 + w] = lo; }
        for (int j = lane; j < cnt && j < 48; j += 32)
            sidx[w * 48 + j] = idx[lo + j];
    }
    __syncthreads();

    int cu = meta[0], ci = meta[1];
    float prod = 0.f;
    int d = tid;
    if (d < DW) {
        float u0 = 0.f, u1 = 0.f, u2 = 0.f, u3 = 0.f;
        float i0 = 0.f, i1 = 0.f, i2 = 0.f, i3 = 0.f;
        int cuc = cu < 48 ? cu : 48;
        int cic = ci < 48 ? ci : 48;
        int c = cuc < cic ? cuc : cic;
        int j = 0;
        for (; j + 4 <= c; j += 4) {
            u0 += g_rs[sidx[j]      * DW + d];
            i0 += g_rs[sidx[48 + j] * DW + d];
            u1 += g_rs[sidx[j + 1]      * DW + d];
            i1 += g_rs[sidx[48 + j + 1] * DW + d];
            u2 += g_rs[sidx[j + 2]      * DW + d];
            i2 += g_rs[sidx[48 + j + 2] * DW + d];
            u3 += g_rs[sidx[j + 3]      * DW + d];
            i3 += g_rs[sidx[48 + j + 3] * DW + d];
        }
        for (int k = j; k < cuc; k++) u0 += g_rs[sidx[k] * DW + d];
        for (int k = j; k < cic; k++) i0 += g_rs[sidx[48 + k] * DW + d];
        for (int k = 48; k < cu; k++) u0 += g_rs[uhi[meta[2] + k] * DW + d];
        for (int k = 48; k < ci; k++) i0 += g_rs[ihi[meta[3] + k] * DW + d];
        float um = ((u0 + u1) + (u2 + u3)) / (float)cu;
        float im = ((i0 + i1) + (i2 + i3)) / (float)ci;
        prod = um * im;
    }
    float s = warp_sum(prod);
    if (lane == 0) red[w] = s;
    __syncthreads();
    if (tid == 0) {
        float t = 0.f;
        #pragma unroll
        for (int k = 0; k < 8; k++) t += red[k];
        float e = t + 3.5f - label[b];
        g_sq[b] = e * e;
        __threadfence();
        rank = atomicAdd(&g_cnt, 1u);
    }
    __syncthreads();

    // -------- last block: final reductions --------
    if (rank == BUSR - 1) {
        __threadfence();
        const float4* h4 = (const float4*)g_hinge;   // 1024 float4
        float hsum = 0.f;
        #pragma unroll
        for (int r = 0; r < 4; r++) {
            float4 hv = h4[tid + 256 * r];
            hsum += (hv.x + hv.y) + (hv.z + hv.w);
        }
        hsum = warp_sum(hsum);
        if (lane == 0) red[w] = hsum;
        __syncthreads();
        float hs = 0.f;
        if (tid == 0) {
            #pragma unroll
            for (int k = 0; k < 8; k++) hs += red[k];
        }
        __syncthreads();

        float4 qv = ((const float4*)g_sq)[tid];      // 256 float4
        float q = (qv.x + qv.y) + (qv.z + qv.w);
        q = warp_sum(q);
        if (lane == 0) red[w] = q;
        __syncthreads();
        if (tid == 0) {
            float rsum = 0.f;
            #pragma unroll
            for (int k = 0; k < 8; k++) rsum += red[k];
            float rating = rsum / (float)BUSR;
            float J = hs / (float)(NREV * NNEG);
            float abae = g_U[0] + J;
            out[0] = rating + abae;
            out[1] = rating;
            out[2] = abae;
            g_cnt = 0u;   // reset for next graph replay
        }
    }
}

// ---------------- launch ------------------------------------------------------
extern "C" void kernel_launch(void* const* d_in, const int* in_sizes, int n_in,
                              void* d_out, int out_size) {
    const int*   hist  = (const int*)d_in[0];
    const float* rpos  = (const float*)d_in[1];
    const float* rneg  = (const float*)d_in[2];
    const float* label = (const float*)d_in[5];
    const int*   uhi   = (const int*)d_in[6];
    const int*   usi   = (const int*)d_in[7];
    const int*   ihi   = (const int*)d_in[8];
    const int*   isi   = (const int*)d_in[9];
    const float* wemb  = (const float*)d_in[10];
    const float* Mw    = (const float*)d_in[11];
    const float* Ww    = (const float*)d_in[12];
    const float* Wb    = (const float*)d_in[13];
    const float* Tw    = (const float*)d_in[14];
    float* out = (float*)d_out;
    int F = in_sizes[6];

    const int SMEM_QK   = (DW * DW + 32 * DW) * 4;   // 185600 B
    const int SMEM_MAIN = SM_WORDS * 4;              // 54432 B
    cudaFuncSetAttribute(qk, cudaFuncAttributeMaxDynamicSharedMemorySize, SMEM_QK);
    cudaFuncSetAttribute(mainkern, cudaFuncAttributeMaxDynamicSharedMemorySize, SMEM_MAIN);

    int prep_elems = (AASP * DW > F) ? AASP * DW : F;
    int prep_blocks = (prep_elems + 511) / 512;
    qk<<<QK_BLOCKS + prep_blocks, 512, SMEM_QK>>>(rpos, Mw, Ww, Tw, usi, isi, F);
    mainkern<<<NREV + 1, 256, SMEM_MAIN>>>(hist, wemb, rneg, Wb, Tw);
    segpred<<<BUSR, 256>>>(uhi, ihi, label, out);
}